// round 11
// baseline (speedup 1.0000x reference)
#include <cuda_runtime.h>
#include <cstdint>

#define DM 64
#define NH 4
#define BB 16
#define TT 1024
#define ROWS_TOTAL (BB*TT)

typedef unsigned long long u64;
typedef unsigned int u32;

__device__ float g_K[ROWS_TOTAL*DM];    // [b,h,t,16]
__device__ float g_V[ROWS_TOTAL*DM];    // [b,h,t,16]
__device__ float g_Q[ROWS_TOTAL*DM];    // [b,h,t,16] (pre-scaled by 0.25*log2e)
__device__ float g_ctx[ROWS_TOTAL*DM];  // [b,t,64]

// ---- packed f32x2 helpers ----
__device__ __forceinline__ u64 pk2(float lo, float hi) {
    u64 d;
    asm("mov.b64 %0,{%1,%2};" : "=l"(d)
        : "r"(__float_as_uint(lo)), "r"(__float_as_uint(hi)));
    return d;
}
__device__ __forceinline__ u64 dup2(float v) {
    u64 d;
    asm("mov.b64 %0,{%1,%1};" : "=l"(d) : "r"(__float_as_uint(v)));
    return d;
}
__device__ __forceinline__ void up2(u64 d, float& lo, float& hi) {
    unsigned a, b;
    asm("mov.b64 {%0,%1},%2;" : "=r"(a), "=r"(b) : "l"(d));
    lo = __uint_as_float(a); hi = __uint_as_float(b);
}
__device__ __forceinline__ u64 fma2(u64 a, u64 b, u64 c) {
    u64 d;
    asm("fma.rn.f32x2 %0,%1,%2,%3;" : "=l"(d) : "l"(a), "l"(b), "l"(c));
    return d;
}
__device__ __forceinline__ u64 mul2(u64 a, u64 b) {
    u64 d;
    asm("mul.rn.f32x2 %0,%1,%2;" : "=l"(d) : "l"(a), "l"(b));
    return d;
}
__device__ __forceinline__ float ex2a(float x) {
    float y;
    asm("ex2.approx.f32 %0,%1;" : "=f"(y) : "f"(x));
    return y;
}
__device__ __forceinline__ u32 smem_u32(const void* p) {
    u32 a;
    asm("{ .reg .u64 t; cvta.to.shared.u64 t, %1; cvt.u32.u64 %0, t; }"
        : "=r"(a) : "l"(p));
    return a;
}
__device__ __forceinline__ void cpasync16(u32 smem, const float* g) {
    u64 ga;
    asm("cvta.to.global.u64 %0, %1;" : "=l"(ga) : "l"(g));
    asm volatile("cp.async.ca.shared.global [%0], [%1], 16;"
                 :: "r"(smem), "l"(ga) : "memory");
}

// ---------------------------------------------------------------------------
// Merged KV + Q projections, row-pair packed f32x2 math.
// Blocks [0,512): kv (32 rows). Blocks [512,1024): q (32 rows).
// X stored transposed as u64 row-pairs: XsT[k][pair], stride 18 u64/k.
// ---------------------------------------------------------------------------
__global__ void __launch_bounds__(256) qkv_kernel(const float* __restrict__ x,
                                                  const float* __restrict__ enc,
                                                  const float* __restrict__ Wkv,
                                                  const float* __restrict__ bkv,
                                                  const float* __restrict__ Wq,
                                                  const float* __restrict__ bq) {
    __shared__ __align__(16) char sm[9216 + 32768];   // XsT [64][18]u64 | Ws
    u64* XsT = (u64*)sm;
    float (*Ws)[128] = (float(*)[128])(sm + 9216);
    float (*Wsq)[64] = (float(*)[64])(sm + 9216);

    if (blockIdx.x < 512) {
        int rowbase = blockIdx.x * 32;
        for (int i = threadIdx.x; i < 64*128/4; i += 256)
            ((float4*)Ws)[i] = ((const float4*)Wkv)[i];
        {   // transpose 32 rows x 64 cols into row-pair u64s
            int r  = threadIdx.x & 15;
            int k0 = (threadIdx.x >> 4) * 4;
            float4 a = *(const float4*)&enc[(rowbase + 2*r    )*64 + k0];
            float4 b = *(const float4*)&enc[(rowbase + 2*r + 1)*64 + k0];
            XsT[(k0+0)*18 + r] = pk2(a.x, b.x);
            XsT[(k0+1)*18 + r] = pk2(a.y, b.y);
            XsT[(k0+2)*18 + r] = pk2(a.z, b.z);
            XsT[(k0+3)*18 + r] = pk2(a.w, b.w);
        }
        __syncthreads();

        int c  = threadIdx.x & 127;
        int rg = threadIdx.x >> 7;        // pairs rg*8 .. rg*8+7
        float bias = bkv[c];
        u64 acc2[8];
#pragma unroll
        for (int j = 0; j < 8; j++) acc2[j] = dup2(bias);

#pragma unroll 4
        for (int k = 0; k < 64; k++) {
            u64 wd = dup2(Ws[k][c]);
            const ulonglong2* xp = (const ulonglong2*)&XsT[k*18 + rg*8];
            ulonglong2 x01 = xp[0], x23 = xp[1], x45 = xp[2], x67 = xp[3];
            acc2[0] = fma2(wd, x01.x, acc2[0]); acc2[1] = fma2(wd, x01.y, acc2[1]);
            acc2[2] = fma2(wd, x23.x, acc2[2]); acc2[3] = fma2(wd, x23.y, acc2[3]);
            acc2[4] = fma2(wd, x45.x, acc2[4]); acc2[5] = fma2(wd, x45.y, acc2[5]);
            acc2[6] = fma2(wd, x67.x, acc2[6]); acc2[7] = fma2(wd, x67.y, acc2[7]);
        }

        int h = (c >> 4) & 3;
        int d = c & 15;
        float* dst = (c < 64) ? g_K : g_V;
#pragma unroll
        for (int j = 0; j < 8; j++) {
            int row = rowbase + 2*(rg*8 + j);
            int b = row >> 10, t = row & 1023;
            float lo, hi;
            up2(acc2[j], lo, hi);
            float* base = &dst[(((b << 2) | h) * 1024 + t) * 16 + d];
            base[0]  = lo;
            base[16] = hi;
        }
    } else {
        const float QS = 0.25f * 1.4426950408889634f;
        int rowbase = (blockIdx.x - 512) * 32;
        for (int i = threadIdx.x; i < 64*64/4; i += 256)
            ((float4*)Wsq)[i] = ((const float4*)Wq)[i];
        {
            int r  = threadIdx.x & 15;
            int k0 = (threadIdx.x >> 4) * 4;
            float4 a = *(const float4*)&x[(rowbase + 2*r    )*64 + k0];
            float4 b = *(const float4*)&x[(rowbase + 2*r + 1)*64 + k0];
            XsT[(k0+0)*18 + r] = pk2(a.x, b.x);
            XsT[(k0+1)*18 + r] = pk2(a.y, b.y);
            XsT[(k0+2)*18 + r] = pk2(a.z, b.z);
            XsT[(k0+3)*18 + r] = pk2(a.w, b.w);
        }
        __syncthreads();

        int c  = threadIdx.x & 63;
        int rg = threadIdx.x >> 6;        // pairs rg*4 .. rg*4+3
        float bias = bq[c];
        u64 acc2[4];
#pragma unroll
        for (int j = 0; j < 4; j++) acc2[j] = dup2(bias);

#pragma unroll 4
        for (int k = 0; k < 64; k++) {
            u64 wd = dup2(Wsq[k][c]);
            const ulonglong2* xp = (const ulonglong2*)&XsT[k*18 + rg*4];
            ulonglong2 x01 = xp[0], x23 = xp[1];
            acc2[0] = fma2(wd, x01.x, acc2[0]); acc2[1] = fma2(wd, x01.y, acc2[1]);
            acc2[2] = fma2(wd, x23.x, acc2[2]); acc2[3] = fma2(wd, x23.y, acc2[3]);
        }

        u64 qs2 = dup2(QS);
        int h = c >> 4;
        int d = c & 15;
#pragma unroll
        for (int j = 0; j < 4; j++) {
            int row = rowbase + 2*(rg*4 + j);
            int b = row >> 10, t = row & 1023;
            float lo, hi;
            up2(mul2(acc2[j], qs2), lo, hi);
            float* base = &g_Q[(((b << 2) | h) * 1024 + t) * 16 + d];
            base[0]  = lo;
            base[16] = hi;
        }
    }
}

// ---------------------------------------------------------------------------
// Attention: single-pass softmax, split-K(2), cp.async double-buffered tiles.
// (unchanged from R10)
// ---------------------------------------------------------------------------
__global__ void __launch_bounds__(256) attn_kernel(const int* __restrict__ mask) {
    __shared__ __align__(16) char smraw[34816];
    u32 smb = smem_u32(smraw);
    float* Pl   = (float*)smraw;
    float* Pacc = (float*)(smraw + 1024);

    int bh  = blockIdx.x;
    int b   = bh >> 2;
    int h   = bh & 3;
    int qt  = blockIdx.y;
    int tid = threadIdx.x;
    int half = tid >> 7;
    int lid  = tid & 127;

    int r0 = qt*256 + lid;

    u64 qa[8], qb[8];
    {
        const ulonglong2* qp0 = (const ulonglong2*)(g_Q + (bh*1024 + r0) * 16);
        const ulonglong2* qp1 = (const ulonglong2*)(g_Q + (bh*1024 + r0 + 128) * 16);
#pragma unroll
        for (int j = 0; j < 4; j++) {
            ulonglong2 t0 = qp0[j]; qa[2*j] = t0.x; qa[2*j+1] = t0.y;
            ulonglong2 t1 = qp1[j]; qb[2*j] = t1.x; qb[2*j+1] = t1.y;
        }
    }

    int row  = lid >> 1;
    int part = lid & 1;

    {
        int kb = half*512;
        const float* gk = g_K + ((bh*1024 + kb + row)*16 + part*8);
        const float* gv = g_V + ((bh*1024 + kb + row)*16 + part*8);
        u32 kd = smb + half*4096 + row*64 + part*32;
        u32 vd = smb + 8192 + half*4096 + row*64 + part*32;
        cpasync16(kd,      gk);
        cpasync16(kd + 16, gk + 4);
        cpasync16(vd,      gv);
        cpasync16(vd + 16, gv + 4);
        asm volatile("cp.async.commit_group;" ::: "memory");
    }
    int mcur = 0, mnext = 0;
    if (lid < 64) mcur = mask[b*1024 + half*512 + lid];

    float l0 = 0.0f, l1 = 0.0f;
    u64 acc0[8], acc1[8];
#pragma unroll
    for (int j = 0; j < 8; j++) { acc0[j] = 0ull; acc1[j] = 0ull; }

    for (int t = 0; t < 8; ++t) {
        int s = t & 1;
        if (t < 7) {
            int kb = half*512 + (t+1)*64;
            if (lid < 64) mnext = mask[b*1024 + kb + lid];
            const float* gk = g_K + ((bh*1024 + kb + row)*16 + part*8);
            const float* gv = g_V + ((bh*1024 + kb + row)*16 + part*8);
            u32 sb = smb + (s^1)*17408;
            u32 kd = sb + half*4096 + row*64 + part*32;
            u32 vd = sb + 8192 + half*4096 + row*64 + part*32;
            cpasync16(kd,      gk);
            cpasync16(kd + 16, gk + 4);
            cpasync16(vd,      gv);
            cpasync16(vd + 16, gv + 4);
            asm volatile("cp.async.commit_group;" ::: "memory");
            asm volatile("cp.async.wait_group 1;" ::: "memory");
        } else {
            asm volatile("cp.async.wait_group 0;" ::: "memory");
        }
        if (lid < 64)
            *(u64*)(smraw + s*17408 + 16384 + half*512 + lid*8) =
                pk2(mcur ? 0.0f : -1e30f, 0.0f);
        __syncthreads();

        const float* Kt = (const float*)(smraw + s*17408 + half*4096);
        const float* Vt = (const float*)(smraw + s*17408 + 8192 + half*4096);
        const u64*   Mt = (const u64*)(smraw + s*17408 + 16384 + half*512);

#pragma unroll 4
        for (int i = 0; i < 64; i++) {
            const ulonglong2* kr = (const ulonglong2*)(Kt + i*16);
            ulonglong2 k0 = kr[0], k1 = kr[1], k2 = kr[2], k3 = kr[3];
            u64 mbv = Mt[i];
            u64 eA = fma2(qa[0], k0.x, mbv);
            eA = fma2(qa[1], k0.y, eA); eA = fma2(qa[2], k1.x, eA);
            eA = fma2(qa[3], k1.y, eA); eA = fma2(qa[4], k2.x, eA);
            eA = fma2(qa[5], k2.y, eA); eA = fma2(qa[6], k3.x, eA);
            eA = fma2(qa[7], k3.y, eA);
            u64 eB = fma2(qb[0], k0.x, mbv);
            eB = fma2(qb[1], k0.y, eB); eB = fma2(qb[2], k1.x, eB);
            eB = fma2(qb[3], k1.y, eB); eB = fma2(qb[4], k2.x, eB);
            eB = fma2(qb[5], k2.y, eB); eB = fma2(qb[6], k3.x, eB);
            eB = fma2(qb[7], k3.y, eB);

            float lo, hi;
            up2(eA, lo, hi); float p0 = ex2a(lo + hi);
            up2(eB, lo, hi); float p1 = ex2a(lo + hi);
            l0 += p0; l1 += p1;
            u64 pd0 = dup2(p0), pd1 = dup2(p1);

            const ulonglong2* vr = (const ulonglong2*)(Vt + i*16);
            ulonglong2 v0 = vr[0], v1 = vr[1], v2 = vr[2], v3 = vr[3];
            acc0[0] = fma2(pd0, v0.x, acc0[0]); acc0[1] = fma2(pd0, v0.y, acc0[1]);
            acc0[2] = fma2(pd0, v1.x, acc0[2]); acc0[3] = fma2(pd0, v1.y, acc0[3]);
            acc0[4] = fma2(pd0, v2.x, acc0[4]); acc0[5] = fma2(pd0, v2.y, acc0[5]);
            acc0[6] = fma2(pd0, v3.x, acc0[6]); acc0[7] = fma2(pd0, v3.y, acc0[7]);
            acc1[0] = fma2(pd1, v0.x, acc1[0]); acc1[1] = fma2(pd1, v0.y, acc1[1]);
            acc1[2] = fma2(pd1, v1.x, acc1[2]); acc1[3] = fma2(pd1, v1.y, acc1[3]);
            acc1[4] = fma2(pd1, v2.x, acc1[4]); acc1[5] = fma2(pd1, v2.y, acc1[5]);
            acc1[6] = fma2(pd1, v3.x, acc1[6]); acc1[7] = fma2(pd1, v3.y, acc1[7]);
        }
        __syncthreads();
        mcur = mnext;
    }

    if (half) {
        Pl[lid]       = l0;
        Pl[lid + 128] = l1;
        float* pa0 = Pacc + lid*17;
        float* pa1 = Pacc + (lid + 128)*17;
#pragma unroll
        for (int j = 0; j < 8; j++) {
            float lo, hi;
            up2(acc0[j], lo, hi); pa0[2*j] = lo; pa0[2*j+1] = hi;
            up2(acc1[j], lo, hi); pa1[2*j] = lo; pa1[2*j+1] = hi;
        }
    }
    __syncthreads();

    if (!half) {
        {
            float inv = 1.0f / (l0 + Pl[lid]);
            const float* pa = Pacc + lid*17;
            float o[16];
#pragma unroll
            for (int j = 0; j < 8; j++) {
                float lo, hi;
                up2(acc0[j], lo, hi);
                o[2*j]   = (lo + pa[2*j])   * inv;
                o[2*j+1] = (hi + pa[2*j+1]) * inv;
            }
            float4* o4 = (float4*)(g_ctx + (b*1024 + r0) * 64 + h*16);
            o4[0] = make_float4(o[0],  o[1],  o[2],  o[3]);
            o4[1] = make_float4(o[4],  o[5],  o[6],  o[7]);
            o4[2] = make_float4(o[8],  o[9],  o[10], o[11]);
            o4[3] = make_float4(o[12], o[13], o[14], o[15]);
        }
        {
            float inv = 1.0f / (l1 + Pl[lid + 128]);
            const float* pa = Pacc + (lid + 128)*17;
            float o[16];
#pragma unroll
            for (int j = 0; j < 8; j++) {
                float lo, hi;
                up2(acc1[j], lo, hi);
                o[2*j]   = (lo + pa[2*j])   * inv;
                o[2*j+1] = (hi + pa[2*j+1]) * inv;
            }
            float4* o4 = (float4*)(g_ctx + (b*1024 + r0 + 128) * 64 + h*16);
            o4[0] = make_float4(o[0],  o[1],  o[2],  o[3]);
            o4[1] = make_float4(o[4],  o[5],  o[6],  o[7]);
            o4[2] = make_float4(o[8],  o[9],  o[10], o[11]);
            o4[3] = make_float4(o[12], o[13], o[14], o[15]);
        }
    }
}

// ---------------------------------------------------------------------------
// Output projection, 64 rows/block, row-pair packed f32x2 math.
// XsT: [64 k][34 u64] (32 pairs + 2 pad), stride keeps 16B alignment.
// ---------------------------------------------------------------------------
__global__ void __launch_bounds__(256) proj_kernel(const float* __restrict__ Wp,
                                                   const float* __restrict__ bp,
                                                   float* __restrict__ out) {
    __shared__ __align__(16) char sm[16384 + 17408];
    float (*Ws)[64] = (float(*)[64])sm;
    u64* XsT = (u64*)(sm + 16384);
    int rowbase = blockIdx.x * 64;

    for (int i = threadIdx.x; i < 64*64/4; i += 256)
        ((float4*)Ws)[i] = ((const float4*)Wp)[i];
    for (int u = threadIdx.x; u < 512; u += 256) {
        int r  = u & 31;
        int k0 = (u >> 5) * 4;
        float4 a = *(const float4*)&g_ctx[(rowbase + 2*r    )*64 + k0];
        float4 b = *(const float4*)&g_ctx[(rowbase + 2*r + 1)*64 + k0];
        XsT[(k0+0)*34 + r] = pk2(a.x, b.x);
        XsT[(k0+1)*34 + r] = pk2(a.y, b.y);
        XsT[(k0+2)*34 + r] = pk2(a.z, b.z);
        XsT[(k0+3)*34 + r] = pk2(a.w, b.w);
    }
    __syncthreads();

    int c  = threadIdx.x & 63;
    int rg = threadIdx.x >> 6;          // pairs rg*8 .. rg*8+7
    float bias = bp[c];
    u64 acc2[8];
#pragma unroll
    for (int j = 0; j < 8; j++) acc2[j] = dup2(bias);

#pragma unroll 4
    for (int k = 0; k < 64; k++) {
        u64 wd = dup2(Ws[k][c]);
        const ulonglong2* xp = (const ulonglong2*)&XsT[k*34 + rg*8];
        ulonglong2 x01 = xp[0], x23 = xp[1], x45 = xp[2], x67 = xp[3];
        acc2[0] = fma2(wd, x01.x, acc2[0]); acc2[1] = fma2(wd, x01.y, acc2[1]);
        acc2[2] = fma2(wd, x23.x, acc2[2]); acc2[3] = fma2(wd, x23.y, acc2[3]);
        acc2[4] = fma2(wd, x45.x, acc2[4]); acc2[5] = fma2(wd, x45.y, acc2[5]);
        acc2[6] = fma2(wd, x67.x, acc2[6]); acc2[7] = fma2(wd, x67.y, acc2[7]);
    }

#pragma unroll
    for (int j = 0; j < 8; j++) {
        int row = rowbase + 2*(rg*8 + j);
        float lo, hi;
        up2(acc2[j], lo, hi);
        out[row*64 + c]       = lo;
        out[(row + 1)*64 + c] = hi;
    }
}

// ---------------------------------------------------------------------------
extern "C" void kernel_launch(void* const* d_in, const int* in_sizes, int n_in,
                              void* d_out, int out_size) {
    const float* x    = (const float*)d_in[0];
    const float* enc  = (const float*)d_in[1];
    const int*   msk  = (const int*)  d_in[2];
    const float* Wkv  = (const float*)d_in[3];
    const float* bkv  = (const float*)d_in[4];
    const float* Wq   = (const float*)d_in[5];
    const float* bq   = (const float*)d_in[6];
    const float* Wp   = (const float*)d_in[7];
    const float* bp   = (const float*)d_in[8];
    float* out = (float*)d_out;

    qkv_kernel<<<1024, 256>>>(x, enc, Wkv, bkv, Wq, bq);
    attn_kernel<<<dim3(BB*NH, TT/256), 256>>>(msk);
    proj_kernel<<<ROWS_TOTAL/64, 256>>>(Wp, bp, out);
}

// round 12
// speedup vs baseline: 1.0002x; 1.0002x over previous
#include <cuda_runtime.h>
#include <cstdint>

#define DM 64
#define NH 4
#define BB 16
#define TT 1024
#define ROWS_TOTAL (BB*TT)

typedef unsigned long long u64;
typedef unsigned int u32;

__device__ float g_K[ROWS_TOTAL*DM];    // [b,h,t,16]
__device__ float g_V[ROWS_TOTAL*DM];    // [b,h,t,16]
__device__ float g_Q[ROWS_TOTAL*DM];    // [b,h,t,16] (pre-scaled by 0.25*log2e)
__device__ float g_ctx[ROWS_TOTAL*DM];  // [b,t,64]

// ---- packed f32x2 helpers ----
__device__ __forceinline__ u64 pk2(float lo, float hi) {
    u64 d;
    asm("mov.b64 %0,{%1,%2};" : "=l"(d)
        : "r"(__float_as_uint(lo)), "r"(__float_as_uint(hi)));
    return d;
}
__device__ __forceinline__ u64 dup2(float v) {
    u64 d;
    asm("mov.b64 %0,{%1,%1};" : "=l"(d) : "r"(__float_as_uint(v)));
    return d;
}
__device__ __forceinline__ void up2(u64 d, float& lo, float& hi) {
    unsigned a, b;
    asm("mov.b64 {%0,%1},%2;" : "=r"(a), "=r"(b) : "l"(d));
    lo = __uint_as_float(a); hi = __uint_as_float(b);
}
__device__ __forceinline__ u64 fma2(u64 a, u64 b, u64 c) {
    u64 d;
    asm("fma.rn.f32x2 %0,%1,%2,%3;" : "=l"(d) : "l"(a), "l"(b), "l"(c));
    return d;
}
__device__ __forceinline__ float ex2a(float x) {
    float y;
    asm("ex2.approx.f32 %0,%1;" : "=f"(y) : "f"(x));
    return y;
}
__device__ __forceinline__ u32 smem_u32(const void* p) {
    u32 a;
    asm("{ .reg .u64 t; cvta.to.shared.u64 t, %1; cvt.u32.u64 %0, t; }"
        : "=r"(a) : "l"(p));
    return a;
}
__device__ __forceinline__ void cpasync16(u32 smem, const float* g) {
    u64 ga;
    asm("cvta.to.global.u64 %0, %1;" : "=l"(ga) : "l"(g));
    asm volatile("cp.async.ca.shared.global [%0], [%1], 16;"
                 :: "r"(smem), "l"(ga) : "memory");
}

// ---------------------------------------------------------------------------
// Merged KV + Q projections, 4 row-tiles of 32 per block, weights loaded once,
// X tiles double-buffered with cp.async.
// Blocks [0,128): kv, rows [blk*128, blk*128+128).
// Blocks [128,256): q, rows [(blk-128)*128, ...+128).
// Smem: Ws @0 (32KB kv / 16KB q), Xs0 @32768 (8KB), Xs1 @40960 (8KB).
// ---------------------------------------------------------------------------
__global__ void __launch_bounds__(256) qkv_kernel(const float* __restrict__ x,
                                                  const float* __restrict__ enc,
                                                  const float* __restrict__ Wkv,
                                                  const float* __restrict__ bkv,
                                                  const float* __restrict__ Wq,
                                                  const float* __restrict__ bq) {
    __shared__ __align__(16) char sm[49152];
    u32 smb = smem_u32(sm);
    int tid = threadIdx.x;

    if (blockIdx.x < 128) {
        // ================= KV =================
        float (*Ws)[128] = (float(*)[128])sm;
        int rowbase0 = blockIdx.x * 128;

        // prologue: X tile 0 via cp.async, then weights
        {
            const float* src = enc + rowbase0*64;
            cpasync16(smb + 32768 + tid*16,        src + tid*4);
            cpasync16(smb + 32768 + (tid+256)*16,  src + (tid+256)*4);
            asm volatile("cp.async.commit_group;" ::: "memory");
        }
        for (int i = tid; i < 64*128/4; i += 256)
            ((float4*)Ws)[i] = ((const float4*)Wkv)[i];

        int c  = tid & 127;
        int rg = tid >> 7;
        float bias = bkv[c];
        int h = (c >> 4) & 3;
        int d = c & 15;
        float* dst = (c < 64) ? g_K : g_V;

        for (int t = 0; t < 4; ++t) {
            int s = t & 1;
            if (t < 3) {
                const float* src = enc + (rowbase0 + (t+1)*32)*64;
                u32 xb = smb + 32768 + (s^1)*8192;
                cpasync16(xb + tid*16,       src + tid*4);
                cpasync16(xb + (tid+256)*16, src + (tid+256)*4);
                asm volatile("cp.async.commit_group;" ::: "memory");
                asm volatile("cp.async.wait_group 1;" ::: "memory");
            } else {
                asm volatile("cp.async.wait_group 0;" ::: "memory");
            }
            __syncthreads();

            const float (*Xs)[64] = (const float(*)[64])(sm + 32768 + s*8192);
            float acc[16];
#pragma unroll
            for (int r = 0; r < 16; r++) acc[r] = bias;
#pragma unroll 4
            for (int k0 = 0; k0 < 64; k0 += 4) {
                float w0 = Ws[k0][c], w1 = Ws[k0+1][c], w2 = Ws[k0+2][c], w3 = Ws[k0+3][c];
#pragma unroll
                for (int r = 0; r < 16; r++) {
                    float4 xv = *(const float4*)&Xs[rg*16 + r][k0];
                    acc[r] += xv.x*w0 + xv.y*w1 + xv.z*w2 + xv.w*w3;
                }
            }
            int rowbase = rowbase0 + t*32;
#pragma unroll
            for (int r = 0; r < 16; r++) {
                int row = rowbase + rg*16 + r;
                int b = row >> 10, tt = row & 1023;
                dst[(((b << 2) | h) * 1024 + tt) * 16 + d] = acc[r];
            }
            __syncthreads();
        }
    } else {
        // ================= Q =================
        const float QS = 0.25f * 1.4426950408889634f;
        float (*Wsq)[64] = (float(*)[64])sm;
        int rowbase0 = (blockIdx.x - 128) * 128;

        {
            const float* src = x + rowbase0*64;
            cpasync16(smb + 32768 + tid*16,        src + tid*4);
            cpasync16(smb + 32768 + (tid+256)*16,  src + (tid+256)*4);
            asm volatile("cp.async.commit_group;" ::: "memory");
        }
        for (int i = tid; i < 64*64/4; i += 256)
            ((float4*)Wsq)[i] = ((const float4*)Wq)[i];

        int c  = tid & 63;
        int rg = tid >> 6;
        float bias = bq[c];
        int h = c >> 4;
        int d = c & 15;

        for (int t = 0; t < 4; ++t) {
            int s = t & 1;
            if (t < 3) {
                const float* src = x + (rowbase0 + (t+1)*32)*64;
                u32 xb = smb + 32768 + (s^1)*8192;
                cpasync16(xb + tid*16,       src + tid*4);
                cpasync16(xb + (tid+256)*16, src + (tid+256)*4);
                asm volatile("cp.async.commit_group;" ::: "memory");
                asm volatile("cp.async.wait_group 1;" ::: "memory");
            } else {
                asm volatile("cp.async.wait_group 0;" ::: "memory");
            }
            __syncthreads();

            const float (*Xs)[64] = (const float(*)[64])(sm + 32768 + s*8192);
            float acc[8];
#pragma unroll
            for (int r = 0; r < 8; r++) acc[r] = bias;
#pragma unroll 4
            for (int k0 = 0; k0 < 64; k0 += 4) {
                float w0 = Wsq[k0][c], w1 = Wsq[k0+1][c], w2 = Wsq[k0+2][c], w3 = Wsq[k0+3][c];
#pragma unroll
                for (int r = 0; r < 8; r++) {
                    float4 xv = *(const float4*)&Xs[rg*8 + r][k0];
                    acc[r] += xv.x*w0 + xv.y*w1 + xv.z*w2 + xv.w*w3;
                }
            }
            int rowbase = rowbase0 + t*32;
#pragma unroll
            for (int r = 0; r < 8; r++) {
                int row = rowbase + rg*8 + r;
                int b = row >> 10, tt = row & 1023;
                g_Q[(((b << 2) | h) * 1024 + tt) * 16 + d] = acc[r] * QS;
            }
            __syncthreads();
        }
    }
}

// ---------------------------------------------------------------------------
// Attention: single-pass softmax, split-K(2), cp.async double-buffered tiles.
// (unchanged from R10)
// ---------------------------------------------------------------------------
__global__ void __launch_bounds__(256) attn_kernel(const int* __restrict__ mask) {
    __shared__ __align__(16) char smraw[34816];
    u32 smb = smem_u32(smraw);
    float* Pl   = (float*)smraw;
    float* Pacc = (float*)(smraw + 1024);

    int bh  = blockIdx.x;
    int b   = bh >> 2;
    int h   = bh & 3;
    int qt  = blockIdx.y;
    int tid = threadIdx.x;
    int half = tid >> 7;
    int lid  = tid & 127;

    int r0 = qt*256 + lid;

    u64 qa[8], qb[8];
    {
        const ulonglong2* qp0 = (const ulonglong2*)(g_Q + (bh*1024 + r0) * 16);
        const ulonglong2* qp1 = (const ulonglong2*)(g_Q + (bh*1024 + r0 + 128) * 16);
#pragma unroll
        for (int j = 0; j < 4; j++) {
            ulonglong2 t0 = qp0[j]; qa[2*j] = t0.x; qa[2*j+1] = t0.y;
            ulonglong2 t1 = qp1[j]; qb[2*j] = t1.x; qb[2*j+1] = t1.y;
        }
    }

    int row  = lid >> 1;
    int part = lid & 1;

    {
        int kb = half*512;
        const float* gk = g_K + ((bh*1024 + kb + row)*16 + part*8);
        const float* gv = g_V + ((bh*1024 + kb + row)*16 + part*8);
        u32 kd = smb + half*4096 + row*64 + part*32;
        u32 vd = smb + 8192 + half*4096 + row*64 + part*32;
        cpasync16(kd,      gk);
        cpasync16(kd + 16, gk + 4);
        cpasync16(vd,      gv);
        cpasync16(vd + 16, gv + 4);
        asm volatile("cp.async.commit_group;" ::: "memory");
    }
    int mcur = 0, mnext = 0;
    if (lid < 64) mcur = mask[b*1024 + half*512 + lid];

    float l0 = 0.0f, l1 = 0.0f;
    u64 acc0[8], acc1[8];
#pragma unroll
    for (int j = 0; j < 8; j++) { acc0[j] = 0ull; acc1[j] = 0ull; }

    for (int t = 0; t < 8; ++t) {
        int s = t & 1;
        if (t < 7) {
            int kb = half*512 + (t+1)*64;
            if (lid < 64) mnext = mask[b*1024 + kb + lid];
            const float* gk = g_K + ((bh*1024 + kb + row)*16 + part*8);
            const float* gv = g_V + ((bh*1024 + kb + row)*16 + part*8);
            u32 sb = smb + (s^1)*17408;
            u32 kd = sb + half*4096 + row*64 + part*32;
            u32 vd = sb + 8192 + half*4096 + row*64 + part*32;
            cpasync16(kd,      gk);
            cpasync16(kd + 16, gk + 4);
            cpasync16(vd,      gv);
            cpasync16(vd + 16, gv + 4);
            asm volatile("cp.async.commit_group;" ::: "memory");
            asm volatile("cp.async.wait_group 1;" ::: "memory");
        } else {
            asm volatile("cp.async.wait_group 0;" ::: "memory");
        }
        if (lid < 64)
            *(u64*)(smraw + s*17408 + 16384 + half*512 + lid*8) =
                pk2(mcur ? 0.0f : -1e30f, 0.0f);
        __syncthreads();

        const float* Kt = (const float*)(smraw + s*17408 + half*4096);
        const float* Vt = (const float*)(smraw + s*17408 + 8192 + half*4096);
        const u64*   Mt = (const u64*)(smraw + s*17408 + 16384 + half*512);

#pragma unroll 4
        for (int i = 0; i < 64; i++) {
            const ulonglong2* kr = (const ulonglong2*)(Kt + i*16);
            ulonglong2 k0 = kr[0], k1 = kr[1], k2 = kr[2], k3 = kr[3];
            u64 mbv = Mt[i];
            u64 eA = fma2(qa[0], k0.x, mbv);
            eA = fma2(qa[1], k0.y, eA); eA = fma2(qa[2], k1.x, eA);
            eA = fma2(qa[3], k1.y, eA); eA = fma2(qa[4], k2.x, eA);
            eA = fma2(qa[5], k2.y, eA); eA = fma2(qa[6], k3.x, eA);
            eA = fma2(qa[7], k3.y, eA);
            u64 eB = fma2(qb[0], k0.x, mbv);
            eB = fma2(qb[1], k0.y, eB); eB = fma2(qb[2], k1.x, eB);
            eB = fma2(qb[3], k1.y, eB); eB = fma2(qb[4], k2.x, eB);
            eB = fma2(qb[5], k2.y, eB); eB = fma2(qb[6], k3.x, eB);
            eB = fma2(qb[7], k3.y, eB);

            float lo, hi;
            up2(eA, lo, hi); float p0 = ex2a(lo + hi);
            up2(eB, lo, hi); float p1 = ex2a(lo + hi);
            l0 += p0; l1 += p1;
            u64 pd0 = dup2(p0), pd1 = dup2(p1);

            const ulonglong2* vr = (const ulonglong2*)(Vt + i*16);
            ulonglong2 v0 = vr[0], v1 = vr[1], v2 = vr[2], v3 = vr[3];
            acc0[0] = fma2(pd0, v0.x, acc0[0]); acc0[1] = fma2(pd0, v0.y, acc0[1]);
            acc0[2] = fma2(pd0, v1.x, acc0[2]); acc0[3] = fma2(pd0, v1.y, acc0[3]);
            acc0[4] = fma2(pd0, v2.x, acc0[4]); acc0[5] = fma2(pd0, v2.y, acc0[5]);
            acc0[6] = fma2(pd0, v3.x, acc0[6]); acc0[7] = fma2(pd0, v3.y, acc0[7]);
            acc1[0] = fma2(pd1, v0.x, acc1[0]); acc1[1] = fma2(pd1, v0.y, acc1[1]);
            acc1[2] = fma2(pd1, v1.x, acc1[2]); acc1[3] = fma2(pd1, v1.y, acc1[3]);
            acc1[4] = fma2(pd1, v2.x, acc1[4]); acc1[5] = fma2(pd1, v2.y, acc1[5]);
            acc1[6] = fma2(pd1, v3.x, acc1[6]); acc1[7] = fma2(pd1, v3.y, acc1[7]);
        }
        __syncthreads();
        mcur = mnext;
    }

    if (half) {
        Pl[lid]       = l0;
        Pl[lid + 128] = l1;
        float* pa0 = Pacc + lid*17;
        float* pa1 = Pacc + (lid + 128)*17;
#pragma unroll
        for (int j = 0; j < 8; j++) {
            float lo, hi;
            up2(acc0[j], lo, hi); pa0[2*j] = lo; pa0[2*j+1] = hi;
            up2(acc1[j], lo, hi); pa1[2*j] = lo; pa1[2*j+1] = hi;
        }
    }
    __syncthreads();

    if (!half) {
        {
            float inv = 1.0f / (l0 + Pl[lid]);
            const float* pa = Pacc + lid*17;
            float o[16];
#pragma unroll
            for (int j = 0; j < 8; j++) {
                float lo, hi;
                up2(acc0[j], lo, hi);
                o[2*j]   = (lo + pa[2*j])   * inv;
                o[2*j+1] = (hi + pa[2*j+1]) * inv;
            }
            float4* o4 = (float4*)(g_ctx + (b*1024 + r0) * 64 + h*16);
            o4[0] = make_float4(o[0],  o[1],  o[2],  o[3]);
            o4[1] = make_float4(o[4],  o[5],  o[6],  o[7]);
            o4[2] = make_float4(o[8],  o[9],  o[10], o[11]);
            o4[3] = make_float4(o[12], o[13], o[14], o[15]);
        }
        {
            float inv = 1.0f / (l1 + Pl[lid + 128]);
            const float* pa = Pacc + (lid + 128)*17;
            float o[16];
#pragma unroll
            for (int j = 0; j < 8; j++) {
                float lo, hi;
                up2(acc1[j], lo, hi);
                o[2*j]   = (lo + pa[2*j])   * inv;
                o[2*j+1] = (hi + pa[2*j+1]) * inv;
            }
            float4* o4 = (float4*)(g_ctx + (b*1024 + r0 + 128) * 64 + h*16);
            o4[0] = make_float4(o[0],  o[1],  o[2],  o[3]);
            o4[1] = make_float4(o[4],  o[5],  o[6],  o[7]);
            o4[2] = make_float4(o[8],  o[9],  o[10], o[11]);
            o4[3] = make_float4(o[12], o[13], o[14], o[15]);
        }
    }
}

// ---------------------------------------------------------------------------
// Output projection, 64 rows/block (R7 version).
// ---------------------------------------------------------------------------
__global__ void __launch_bounds__(256) proj_kernel(const float* __restrict__ Wp,
                                                   const float* __restrict__ bp,
                                                   float* __restrict__ out) {
    __shared__ float Xs[64][64];
    __shared__ float Ws[64][64];
    int rowbase = blockIdx.x * 64;

    for (int i = threadIdx.x; i < 64*64/4; i += 256) {
        ((float4*)Ws)[i] = ((const float4*)Wp)[i];
        ((float4*)Xs)[i] = ((const float4*)g_ctx)[rowbase*16 + i];
    }
    __syncthreads();

    int c  = threadIdx.x & 63;
    int rg = threadIdx.x >> 6;
    float bias = bp[c];
    float acc[16];
#pragma unroll
    for (int r = 0; r < 16; r++) acc[r] = bias;
#pragma unroll 4
    for (int k0 = 0; k0 < 64; k0 += 4) {
        float w0 = Ws[k0][c], w1 = Ws[k0+1][c], w2 = Ws[k0+2][c], w3 = Ws[k0+3][c];
#pragma unroll
        for (int r = 0; r < 16; r++) {
            float4 xv = *(const float4*)&Xs[rg*16 + r][k0];
            acc[r] += xv.x*w0 + xv.y*w1 + xv.z*w2 + xv.w*w3;
        }
    }
#pragma unroll
    for (int r = 0; r < 16; r++)
        out[(rowbase + rg*16 + r) * 64 + c] = acc[r];
}

// ---------------------------------------------------------------------------
extern "C" void kernel_launch(void* const* d_in, const int* in_sizes, int n_in,
                              void* d_out, int out_size) {
    const float* x    = (const float*)d_in[0];
    const float* enc  = (const float*)d_in[1];
    const int*   msk  = (const int*)  d_in[2];
    const float* Wkv  = (const float*)d_in[3];
    const float* bkv  = (const float*)d_in[4];
    const float* Wq   = (const float*)d_in[5];
    const float* bq   = (const float*)d_in[6];
    const float* Wp   = (const float*)d_in[7];
    const float* bp   = (const float*)d_in[8];
    float* out = (float*)d_out;

    qkv_kernel<<<256, 256>>>(x, enc, Wkv, bkv, Wq, bq);
    attn_kernel<<<dim3(BB*NH, TT/256), 256>>>(msk);
    proj_kernel<<<ROWS_TOTAL/64, 256>>>(Wp, bp, out);
}

// round 14
// speedup vs baseline: 1.5274x; 1.5271x over previous
#include <cuda_runtime.h>
#include <cuda_bf16.h>
#include <cstdint>

#define DM 64
#define NH 4
#define BB 16
#define TT 1024
#define ROWS_TOTAL (BB*TT)
#define HEADROWS (ROWS_TOTAL*4)      // 64 bh x 1024 t

typedef unsigned long long u64;
typedef unsigned int u32;

// bf16 hi/lo decompositions, written by qkv_kernel. Each holds 64 bh x 1024 x 16.
__device__ __align__(16) __nv_bfloat16 g_Kh[HEADROWS*16];   // [bh][t][d]
__device__ __align__(16) __nv_bfloat16 g_Kl[HEADROWS*16];
__device__ __align__(16) __nv_bfloat16 g_Vth[HEADROWS*16];  // [bh][d][t] (transposed)
__device__ __align__(16) __nv_bfloat16 g_Vtl[HEADROWS*16];
__device__ __align__(16) __nv_bfloat16 g_Qh[HEADROWS*16];   // [bh][t][d], pre-scaled
__device__ __align__(16) __nv_bfloat16 g_Ql[HEADROWS*16];
__device__ __align__(16) float g_mb[BB*TT];                 // mask bias (0 / -1e30)
__device__ __align__(16) float g_ctx[ROWS_TOTAL*DM];        // [b,t,64]

// ---- helpers ----
__device__ __forceinline__ float ex2a(float x) {
    float y; asm("ex2.approx.f32 %0,%1;" : "=f"(y) : "f"(x)); return y;
}
__device__ __forceinline__ u32 smem_u32(const void* p) {
    u32 a;
    asm("{ .reg .u64 t; cvta.to.shared.u64 t, %1; cvt.u32.u64 %0, t; }"
        : "=r"(a) : "l"(p));
    return a;
}
__device__ __forceinline__ void cpasync16(u32 smem, const void* g) {
    u64 ga;
    asm("cvta.to.global.u64 %0, %1;" : "=l"(ga) : "l"(g));
    asm volatile("cp.async.ca.shared.global [%0], [%1], 16;"
                 :: "r"(smem), "l"(ga) : "memory");
}
// pack two f32 -> bf16x2 (lo element in bits[15:0])
__device__ __forceinline__ u32 pkbf(float lo, float hi) {
    u32 d;
    asm("cvt.rn.bf16x2.f32 %0, %1, %2;" : "=r"(d) : "f"(hi), "f"(lo));
    return d;
}
// m16n8k16 bf16 MMA, fp32 accumulate
__device__ __forceinline__ void mma16816(float& c0, float& c1, float& c2, float& c3,
                                         u32 a0, u32 a1, u32 a2, u32 a3,
                                         u32 b0, u32 b1) {
    asm("mma.sync.aligned.m16n8k16.row.col.f32.bf16.bf16.f32 "
        "{%0,%1,%2,%3}, {%4,%5,%6,%7}, {%8,%9}, {%0,%1,%2,%3};"
        : "+f"(c0), "+f"(c1), "+f"(c2), "+f"(c3)
        : "r"(a0), "r"(a1), "r"(a2), "r"(a3), "r"(b0), "r"(b1));
}

// ---------------------------------------------------------------------------
// Merged KV + Q projections -> bf16 hi/lo outputs; also fills g_mb.
// Blocks [0,512): kv. Blocks [512,1024): q.
// ---------------------------------------------------------------------------
__global__ void __launch_bounds__(256) qkv_kernel(const float* __restrict__ x,
                                                  const float* __restrict__ enc,
                                                  const int*   __restrict__ mask,
                                                  const float* __restrict__ Wkv,
                                                  const float* __restrict__ bkv,
                                                  const float* __restrict__ Wq,
                                                  const float* __restrict__ bq) {
    __shared__ float smem[32*64 + 64*128];
    float (*Xs)[64]  = (float(*)[64])smem;
    float (*Ws)[128] = (float(*)[128])(smem + 32*64);
    float (*Wsq)[64] = (float(*)[64])(smem + 32*64);

    {
        int gid = blockIdx.x*256 + threadIdx.x;
        if (gid < BB*TT) g_mb[gid] = mask[gid] ? 0.0f : -1e30f;
    }

    if (blockIdx.x < 512) {
        int rowbase = blockIdx.x * 32;
        for (int i = threadIdx.x; i < 64*128/4; i += 256)
            ((float4*)Ws)[i] = ((const float4*)Wkv)[i];
        for (int i = threadIdx.x; i < 32*64/4; i += 256)
            ((float4*)Xs)[i] = ((const float4*)enc)[rowbase*16 + i];
        __syncthreads();

        int c  = threadIdx.x & 127;
        int rg = threadIdx.x >> 7;
        float bias = bkv[c];
        float acc[16];
#pragma unroll
        for (int r = 0; r < 16; r++) acc[r] = bias;
#pragma unroll 4
        for (int k0 = 0; k0 < 64; k0 += 4) {
            float w0 = Ws[k0][c], w1 = Ws[k0+1][c], w2 = Ws[k0+2][c], w3 = Ws[k0+3][c];
#pragma unroll
            for (int r = 0; r < 16; r++) {
                float4 xv = *(const float4*)&Xs[rg*16 + r][k0];
                acc[r] += xv.x*w0 + xv.y*w1 + xv.z*w2 + xv.w*w3;
            }
        }
        int h = (c >> 4) & 3;
        int d = c & 15;
#pragma unroll
        for (int r = 0; r < 16; r++) {
            int row = rowbase + rg*16 + r;
            int b = row >> 10, tt = row & 1023;
            float v = acc[r];
            __nv_bfloat16 hi = __float2bfloat16(v);
            float lo_f = v - __uint_as_float((u32)(*(unsigned short*)&hi) << 16);
            __nv_bfloat16 lo = __float2bfloat16(lo_f);
            int bh = (b << 2) | h;
            if (c < 64) {
                int idx = (bh * 1024 + tt) * 16 + d;
                g_Kh[idx] = hi; g_Kl[idx] = lo;
            } else {
                int idx = (bh * 16 + d) * 1024 + tt;
                g_Vth[idx] = hi; g_Vtl[idx] = lo;
            }
        }
    } else {
        const float QS = 0.25f * 1.4426950408889634f;
        int rowbase = (blockIdx.x - 512) * 32;
        for (int i = threadIdx.x; i < 64*64/4; i += 256)
            ((float4*)Wsq)[i] = ((const float4*)Wq)[i];
        for (int i = threadIdx.x; i < 32*64/4; i += 256)
            ((float4*)Xs)[i]  = ((const float4*)x)[rowbase*16 + i];
        __syncthreads();

        int c  = threadIdx.x & 63;
        int rg = threadIdx.x >> 6;
        float bias = bq[c];
        float acc[8];
#pragma unroll
        for (int r = 0; r < 8; r++) acc[r] = bias;
#pragma unroll 4
        for (int k0 = 0; k0 < 64; k0 += 4) {
            float w0 = Wsq[k0][c], w1 = Wsq[k0+1][c], w2 = Wsq[k0+2][c], w3 = Wsq[k0+3][c];
#pragma unroll
            for (int r = 0; r < 8; r++) {
                float4 xv = *(const float4*)&Xs[rg*8 + r][k0];
                acc[r] += xv.x*w0 + xv.y*w1 + xv.z*w2 + xv.w*w3;
            }
        }
        int h = c >> 4;
        int d = c & 15;
#pragma unroll
        for (int r = 0; r < 8; r++) {
            int row = rowbase + rg*8 + r;
            int b = row >> 10, tt = row & 1023;
            float v = acc[r] * QS;
            __nv_bfloat16 hi = __float2bfloat16(v);
            float lo_f = v - __uint_as_float((u32)(*(unsigned short*)&hi) << 16);
            __nv_bfloat16 lo = __float2bfloat16(lo_f);
            int idx = (((b << 2) | h) * 1024 + tt) * 16 + d;
            g_Qh[idx] = hi; g_Ql[idx] = lo;
        }
    }
}

// ---------------------------------------------------------------------------
// Attention via mma.sync m16n8k16 bf16 (3-way hi/lo split), single-pass
// softmax with mask bias as C-initializer.
// grid (64 bh, 8 qtile), block 256 = 8 warps; warp w owns 16 q-rows.
// ---------------------------------------------------------------------------
#define ST_KHI  0
#define ST_KLO  3072
#define ST_VTHI 6144
#define ST_VTLO 8448
#define ST_MB   10752
#define ST_SZ   11008

__global__ void __launch_bounds__(256) attn_kernel() {
    __shared__ __align__(16) char sm[2*ST_SZ];
    u32 smb = smem_u32(sm);

    int bh  = blockIdx.x;
    int b   = bh >> 2;
    int h   = bh & 3;
    int qt  = blockIdx.y;
    int tid = threadIdx.x;
    int w    = tid >> 5;
    int lane = tid & 31;
    int g    = lane >> 2;
    int t    = lane & 3;

    int qrow = qt*128 + w*16 + g;
    const __nv_bfloat16* Qh = g_Qh + (u64)bh*1024*16;
    const __nv_bfloat16* Ql = g_Ql + (u64)bh*1024*16;
    u32 qh0 = *(const u32*)(Qh + qrow*16     + 2*t);
    u32 qh1 = *(const u32*)(Qh + (qrow+8)*16 + 2*t);
    u32 qh2 = *(const u32*)(Qh + qrow*16     + 2*t + 8);
    u32 qh3 = *(const u32*)(Qh + (qrow+8)*16 + 2*t + 8);
    u32 ql0 = *(const u32*)(Ql + qrow*16     + 2*t);
    u32 ql1 = *(const u32*)(Ql + (qrow+8)*16 + 2*t);
    u32 ql2 = *(const u32*)(Ql + qrow*16     + 2*t + 8);
    u32 ql3 = *(const u32*)(Ql + (qrow+8)*16 + 2*t + 8);

    float ctx0[4] = {0,0,0,0}, ctx1[4] = {0,0,0,0};
    float lA = 0.0f, lB = 0.0f;

    const __nv_bfloat16* Khg  = g_Kh  + (u64)bh*1024*16;
    const __nv_bfloat16* Klg  = g_Kl  + (u64)bh*1024*16;
    const __nv_bfloat16* Vthg = g_Vth + (u64)bh*16*1024;
    const __nv_bfloat16* Vtlg = g_Vtl + (u64)bh*16*1024;
    const float* mbg = g_mb + b*1024;

    auto load_tile = [&](int kb, int stage) {
        u32 sb = smb + stage*ST_SZ;
        for (int j = tid; j < 528; j += 256) {
            if (j < 128) {
                int key = j >> 1, part = j & 1;
                cpasync16(sb + ST_KHI + key*48 + part*16,
                          Khg + (kb + key)*16 + part*8);
            } else if (j < 256) {
                int j2 = j - 128, key = j2 >> 1, part = j2 & 1;
                cpasync16(sb + ST_KLO + key*48 + part*16,
                          Klg + (kb + key)*16 + part*8);
            } else if (j < 384) {
                int j2 = j - 256, dd = j2 >> 3, part = j2 & 7;
                cpasync16(sb + ST_VTHI + dd*144 + part*16,
                          Vthg + dd*1024 + kb + part*8);
            } else if (j < 512) {
                int j2 = j - 384, dd = j2 >> 3, part = j2 & 7;
                cpasync16(sb + ST_VTLO + dd*144 + part*16,
                          Vtlg + dd*1024 + kb + part*8);
            } else {
                int m = j - 512;
                cpasync16(sb + ST_MB + m*16, mbg + kb + m*4);
            }
        }
        asm volatile("cp.async.commit_group;" ::: "memory");
    };

    load_tile(0, 0);

    for (int tile = 0; tile < 16; ++tile) {
        int s = tile & 1;
        if (tile < 15) {
            load_tile((tile+1)*64, s^1);
            asm volatile("cp.async.wait_group 1;" ::: "memory");
        } else {
            asm volatile("cp.async.wait_group 0;" ::: "memory");
        }
        __syncthreads();

        const char* st = sm + s*ST_SZ;

#pragma unroll
        for (int c4 = 0; c4 < 4; ++c4) {
            int cb = c4*16;
            const char* k0p = st + ST_KHI + (cb+g)*48   + t*4;
            const char* k1p = st + ST_KHI + (cb+8+g)*48 + t*4;
            u32 kh0a = *(const u32*)k0p,        kh0b = *(const u32*)(k0p+16);
            u32 kh1a = *(const u32*)k1p,        kh1b = *(const u32*)(k1p+16);
            const char* l0p = st + ST_KLO + (cb+g)*48   + t*4;
            const char* l1p = st + ST_KLO + (cb+8+g)*48 + t*4;
            u32 kl0a = *(const u32*)l0p,        kl0b = *(const u32*)(l0p+16);
            u32 kl1a = *(const u32*)l1p,        kl1b = *(const u32*)(l1p+16);

            float2 mbv0 = *(const float2*)(st + ST_MB + (cb + 2*t)*4);
            float2 mbv1 = *(const float2*)(st + ST_MB + (cb + 8 + 2*t)*4);

            float s00 = mbv0.x, s01 = mbv0.y, s02 = mbv0.x, s03 = mbv0.y;
            mma16816(s00,s01,s02,s03, qh0,qh1,qh2,qh3, kh0a,kh0b);
            mma16816(s00,s01,s02,s03, qh0,qh1,qh2,qh3, kl0a,kl0b);
            mma16816(s00,s01,s02,s03, ql0,ql1,ql2,ql3, kh0a,kh0b);
            float s10 = mbv1.x, s11 = mbv1.y, s12 = mbv1.x, s13 = mbv1.y;
            mma16816(s10,s11,s12,s13, qh0,qh1,qh2,qh3, kh1a,kh1b);
            mma16816(s10,s11,s12,s13, qh0,qh1,qh2,qh3, kl1a,kl1b);
            mma16816(s10,s11,s12,s13, ql0,ql1,ql2,ql3, kh1a,kh1b);

            float p00 = ex2a(s00), p01 = ex2a(s01), p02 = ex2a(s02), p03 = ex2a(s03);
            float p10 = ex2a(s10), p11 = ex2a(s11), p12 = ex2a(s12), p13 = ex2a(s13);
            lA += p00 + p01 + p10 + p11;
            lB += p02 + p03 + p12 + p13;

            u32 ph0 = pkbf(p00, p01), ph1 = pkbf(p02, p03);
            u32 ph2 = pkbf(p10, p11), ph3 = pkbf(p12, p13);
            float q00 = p00 - __uint_as_float(ph0 << 16);
            float q01 = p01 - __uint_as_float(ph0 & 0xffff0000u);
            float q02 = p02 - __uint_as_float(ph1 << 16);
            float q03 = p03 - __uint_as_float(ph1 & 0xffff0000u);
            float q10 = p10 - __uint_as_float(ph2 << 16);
            float q11 = p11 - __uint_as_float(ph2 & 0xffff0000u);
            float q12 = p12 - __uint_as_float(ph3 << 16);
            float q13 = p13 - __uint_as_float(ph3 & 0xffff0000u);
            u32 pl0 = pkbf(q00, q01), pl1 = pkbf(q02, q03);
            u32 pl2 = pkbf(q10, q11), pl3 = pkbf(q12, q13);

            const char* v0p = st + ST_VTHI + g*144     + (cb + 2*t)*2;
            const char* v1p = st + ST_VTHI + (8+g)*144 + (cb + 2*t)*2;
            u32 vh0a = *(const u32*)v0p,        vh0b = *(const u32*)(v0p+16);
            u32 vh1a = *(const u32*)v1p,        vh1b = *(const u32*)(v1p+16);
            const char* w0p = st + ST_VTLO + g*144     + (cb + 2*t)*2;
            const char* w1p = st + ST_VTLO + (8+g)*144 + (cb + 2*t)*2;
            u32 vl0a = *(const u32*)w0p,        vl0b = *(const u32*)(w0p+16);
            u32 vl1a = *(const u32*)w1p,        vl1b = *(const u32*)(w1p+16);

            mma16816(ctx0[0],ctx0[1],ctx0[2],ctx0[3], ph0,ph1,ph2,ph3, vh0a,vh0b);
            mma16816(ctx0[0],ctx0[1],ctx0[2],ctx0[3], ph0,ph1,ph2,ph3, vl0a,vl0b);
            mma16816(ctx0[0],ctx0[1],ctx0[2],ctx0[3], pl0,pl1,pl2,pl3, vh0a,vh0b);
            mma16816(ctx1[0],ctx1[1],ctx1[2],ctx1[3], ph0,ph1,ph2,ph3, vh1a,vh1b);
            mma16816(ctx1[0],ctx1[1],ctx1[2],ctx1[3], ph0,ph1,ph2,ph3, vl1a,vl1b);
            mma16816(ctx1[0],ctx1[1],ctx1[2],ctx1[3], pl0,pl1,pl2,pl3, vh1a,vh1b);
        }
        __syncthreads();
    }

    lA += __shfl_xor_sync(0xffffffffu, lA, 1);
    lA += __shfl_xor_sync(0xffffffffu, lA, 2);
    lB += __shfl_xor_sync(0xffffffffu, lB, 1);
    lB += __shfl_xor_sync(0xffffffffu, lB, 2);
    float invA = 1.0f / lA;
    float invB = 1.0f / lB;

    int rowA = qt*128 + w*16 + g;
    int rowB = rowA + 8;
    float* outA = g_ctx + ((u64)b*1024 + rowA)*64 + h*16;
    float* outB = g_ctx + ((u64)b*1024 + rowB)*64 + h*16;
    *(float2*)(outA + 2*t)     = make_float2(ctx0[0]*invA, ctx0[1]*invA);
    *(float2*)(outA + 2*t + 8) = make_float2(ctx1[0]*invA, ctx1[1]*invA);
    *(float2*)(outB + 2*t)     = make_float2(ctx0[2]*invB, ctx0[3]*invB);
    *(float2*)(outB + 2*t + 8) = make_float2(ctx1[2]*invB, ctx1[3]*invB);
}

// ---------------------------------------------------------------------------
// Output projection, 64 rows/block.
// ---------------------------------------------------------------------------
__global__ void __launch_bounds__(256) proj_kernel(const float* __restrict__ Wp,
                                                   const float* __restrict__ bp,
                                                   float* __restrict__ out) {
    __shared__ float Xs[64][64];
    __shared__ float Ws[64][64];
    int rowbase = blockIdx.x * 64;

    for (int i = threadIdx.x; i < 64*64/4; i += 256) {
        ((float4*)Ws)[i] = ((const float4*)Wp)[i];
        ((float4*)Xs)[i] = ((const float4*)g_ctx)[rowbase*16 + i];
    }
    __syncthreads();

    int c  = threadIdx.x & 63;
    int rg = threadIdx.x >> 6;
    float bias = bp[c];
    float acc[16];
#pragma unroll
    for (int r = 0; r < 16; r++) acc[r] = bias;
#pragma unroll 4
    for (int k0 = 0; k0 < 64; k0 += 4) {
        float w0 = Ws[k0][c], w1 = Ws[k0+1][c], w2 = Ws[k0+2][c], w3 = Ws[k0+3][c];
#pragma unroll
        for (int r = 0; r < 16; r++) {
            float4 xv = *(const float4*)&Xs[rg*16 + r][k0];
            acc[r] += xv.x*w0 + xv.y*w1 + xv.z*w2 + xv.w*w3;
        }
    }
#pragma unroll
    for (int r = 0; r < 16; r++)
        out[(rowbase + rg*16 + r) * 64 + c] = acc[r];
}

// ---------------------------------------------------------------------------
extern "C" void kernel_launch(void* const* d_in, const int* in_sizes, int n_in,
                              void* d_out, int out_size) {
    const float* x    = (const float*)d_in[0];
    const float* enc  = (const float*)d_in[1];
    const int*   msk  = (const int*)  d_in[2];
    const float* Wkv  = (const float*)d_in[3];
    const float* bkv  = (const float*)d_in[4];
    const float* Wq   = (const float*)d_in[5];
    const float* bq   = (const float*)d_in[6];
    const float* Wp   = (const float*)d_in[7];
    const float* bp   = (const float*)d_in[8];
    float* out = (float*)d_out;

    qkv_kernel<<<1024, 256>>>(x, enc, msk, Wkv, bkv, Wq, bq);
    attn_kernel<<<dim3(BB*NH, TT/128), 256>>>();
    proj_kernel<<<ROWS_TOTAL/64, 256>>>(Wp, bp, out);
}

// round 15
// speedup vs baseline: 1.7078x; 1.1181x over previous
#include <cuda_runtime.h>
#include <cuda_bf16.h>
#include <cstdint>

#define DM 64
#define NH 4
#define BB 16
#define TT 1024
#define ROWS_TOTAL (BB*TT)
#define HEADROWS (ROWS_TOTAL*4)      // 64 bh x 1024 t

typedef unsigned long long u64;
typedef unsigned int u32;

// bf16 hi/lo decompositions, written by qkv_kernel. Each holds 64 bh x 1024 x 16.
__device__ __align__(16) __nv_bfloat16 g_Kh[HEADROWS*16];   // [bh][t][d]
__device__ __align__(16) __nv_bfloat16 g_Kl[HEADROWS*16];
__device__ __align__(16) __nv_bfloat16 g_Vth[HEADROWS*16];  // [bh][d][t] (transposed)
__device__ __align__(16) __nv_bfloat16 g_Vtl[HEADROWS*16];
__device__ __align__(16) __nv_bfloat16 g_Qh[HEADROWS*16];   // [bh][t][d], pre-scaled
__device__ __align__(16) __nv_bfloat16 g_Ql[HEADROWS*16];
__device__ __align__(16) float g_mb[BB*TT];                 // mask bias (0 / -1e30)
__device__ __align__(16) float g_ctx[ROWS_TOTAL*DM];        // [b,t,64]

// ---- helpers ----
__device__ __forceinline__ float ex2a(float x) {
    float y; asm("ex2.approx.f32 %0,%1;" : "=f"(y) : "f"(x)); return y;
}
__device__ __forceinline__ u32 smem_u32(const void* p) {
    u32 a;
    asm("{ .reg .u64 t; cvta.to.shared.u64 t, %1; cvt.u32.u64 %0, t; }"
        : "=r"(a) : "l"(p));
    return a;
}
__device__ __forceinline__ void cpasync16(u32 smem, const void* g) {
    u64 ga;
    asm("cvta.to.global.u64 %0, %1;" : "=l"(ga) : "l"(g));
    asm volatile("cp.async.ca.shared.global [%0], [%1], 16;"
                 :: "r"(smem), "l"(ga) : "memory");
}
// pack two f32 -> bf16x2 (first arg lands in bits[15:0])
__device__ __forceinline__ u32 pkbf(float lo, float hi) {
    u32 d;
    asm("cvt.rn.bf16x2.f32 %0, %1, %2;" : "=r"(d) : "f"(hi), "f"(lo));
    return d;
}
// hi/lo split of a value pair -> two packed u32
__device__ __forceinline__ void split_pair(float v0, float v1, u32& hp, u32& lp) {
    hp = pkbf(v0, v1);
    float l0 = v0 - __uint_as_float(hp << 16);
    float l1 = v1 - __uint_as_float(hp & 0xffff0000u);
    lp = pkbf(l0, l1);
}
// m16n8k16 bf16 MMA, fp32 accumulate
__device__ __forceinline__ void mma16816(float& c0, float& c1, float& c2, float& c3,
                                         u32 a0, u32 a1, u32 a2, u32 a3,
                                         u32 b0, u32 b1) {
    asm("mma.sync.aligned.m16n8k16.row.col.f32.bf16.bf16.f32 "
        "{%0,%1,%2,%3}, {%4,%5,%6,%7}, {%8,%9}, {%0,%1,%2,%3};"
        : "+f"(c0), "+f"(c1), "+f"(c2), "+f"(c3)
        : "r"(a0), "r"(a1), "r"(a2), "r"(a3), "r"(b0), "r"(b1));
}

// ---------------------------------------------------------------------------
// Merged KV + Q projections -> bf16 hi/lo, all stores u32-packed.
// Blocks [0,512): kv, 32 rows, thread = column PAIR (2p,2p+1) x 8 rows.
// Blocks [512,1024): q, 32 rows, thread = column pair x 4 rows.
// ---------------------------------------------------------------------------
__global__ void __launch_bounds__(256) qkv_kernel(const float* __restrict__ x,
                                                  const float* __restrict__ enc,
                                                  const int*   __restrict__ mask,
                                                  const float* __restrict__ Wkv,
                                                  const float* __restrict__ bkv,
                                                  const float* __restrict__ Wq,
                                                  const float* __restrict__ bq) {
    __shared__ float smem[32*64 + 64*128];
    float (*Xs)[64]  = (float(*)[64])smem;
    float (*Ws)[128] = (float(*)[128])(smem + 32*64);
    float (*Wsq)[64] = (float(*)[64])(smem + 32*64);

    {
        int gid = blockIdx.x*256 + threadIdx.x;
        if (gid < BB*TT) g_mb[gid] = mask[gid] ? 0.0f : -1e30f;
    }

    if (blockIdx.x < 512) {
        int rowbase = blockIdx.x * 32;
        for (int i = threadIdx.x; i < 64*128/4; i += 256)
            ((float4*)Ws)[i] = ((const float4*)Wkv)[i];
        for (int i = threadIdx.x; i < 32*64/4; i += 256)
            ((float4*)Xs)[i] = ((const float4*)enc)[rowbase*16 + i];
        __syncthreads();

        int pr = threadIdx.x & 63;     // column pair: cols 2pr, 2pr+1
        int rg = threadIdx.x >> 6;     // 0..3 -> 8 rows each
        int c0 = 2*pr;
        float2 bias = *(const float2*)&bkv[c0];
        float acc0[8], acc1[8];
#pragma unroll
        for (int r = 0; r < 8; r++) { acc0[r] = bias.x; acc1[r] = bias.y; }

#pragma unroll 4
        for (int k0 = 0; k0 < 64; k0 += 4) {
            float2 wA = *(const float2*)&Ws[k0  ][c0];
            float2 wB = *(const float2*)&Ws[k0+1][c0];
            float2 wC = *(const float2*)&Ws[k0+2][c0];
            float2 wD = *(const float2*)&Ws[k0+3][c0];
#pragma unroll
            for (int r = 0; r < 8; r++) {
                float4 xv = *(const float4*)&Xs[rg*8 + r][k0];
                acc0[r] += xv.x*wA.x + xv.y*wB.x + xv.z*wC.x + xv.w*wD.x;
                acc1[r] += xv.x*wA.y + xv.y*wB.y + xv.z*wC.y + xv.w*wD.y;
            }
        }

        int h = (c0 >> 4) & 3;
        int d = c0 & 15;               // even
        if (pr < 32) {
            // K: pack column pair (d, d+1) per row
#pragma unroll
            for (int r = 0; r < 8; r++) {
                int row = rowbase + rg*8 + r;
                int b = row >> 10, tt = row & 1023;
                int idx = ((((b << 2) | h) * 1024 + tt) * 16 + d);
                u32 hp, lp;
                split_pair(acc0[r], acc1[r], hp, lp);
                *(u32*)&g_Kh[idx] = hp;
                *(u32*)&g_Kl[idx] = lp;
            }
        } else {
            // V transposed [bh][d][t]: pack row pair (tt, tt+1) per column
#pragma unroll
            for (int r = 0; r < 8; r += 2) {
                int row = rowbase + rg*8 + r;     // even
                int b = row >> 10, tt = row & 1023;
                int bh = (b << 2) | h;
                u32 hp0, lp0, hp1, lp1;
                split_pair(acc0[r], acc0[r+1], hp0, lp0);
                split_pair(acc1[r], acc1[r+1], hp1, lp1);
                int i0 = (bh * 16 + d)     * 1024 + tt;
                int i1 = (bh * 16 + d + 1) * 1024 + tt;
                *(u32*)&g_Vth[i0] = hp0; *(u32*)&g_Vtl[i0] = lp0;
                *(u32*)&g_Vth[i1] = hp1; *(u32*)&g_Vtl[i1] = lp1;
            }
        }
    } else {
        const float QS = 0.25f * 1.4426950408889634f;
        int rowbase = (blockIdx.x - 512) * 32;
        for (int i = threadIdx.x; i < 64*64/4; i += 256)
            ((float4*)Wsq)[i] = ((const float4*)Wq)[i];
        for (int i = threadIdx.x; i < 32*64/4; i += 256)
            ((float4*)Xs)[i]  = ((const float4*)x)[rowbase*16 + i];
        __syncthreads();

        int pr = threadIdx.x & 31;     // column pair: cols 2pr, 2pr+1
        int rg = threadIdx.x >> 5;     // 0..7 -> 4 rows each
        int c0 = 2*pr;
        float2 bias = *(const float2*)&bq[c0];
        float acc0[4], acc1[4];
#pragma unroll
        for (int r = 0; r < 4; r++) { acc0[r] = bias.x; acc1[r] = bias.y; }

#pragma unroll 4
        for (int k0 = 0; k0 < 64; k0 += 4) {
            float2 wA = *(const float2*)&Wsq[k0  ][c0];
            float2 wB = *(const float2*)&Wsq[k0+1][c0];
            float2 wC = *(const float2*)&Wsq[k0+2][c0];
            float2 wD = *(const float2*)&Wsq[k0+3][c0];
#pragma unroll
            for (int r = 0; r < 4; r++) {
                float4 xv = *(const float4*)&Xs[rg*4 + r][k0];
                acc0[r] += xv.x*wA.x + xv.y*wB.x + xv.z*wC.x + xv.w*wD.x;
                acc1[r] += xv.x*wA.y + xv.y*wB.y + xv.z*wC.y + xv.w*wD.y;
            }
        }

        int h = c0 >> 4;
        int d = c0 & 15;
#pragma unroll
        for (int r = 0; r < 4; r++) {
            int row = rowbase + rg*4 + r;
            int b = row >> 10, tt = row & 1023;
            int idx = ((((b << 2) | h) * 1024 + tt) * 16 + d);
            u32 hp, lp;
            split_pair(acc0[r] * QS, acc1[r] * QS, hp, lp);
            *(u32*)&g_Qh[idx] = hp;
            *(u32*)&g_Ql[idx] = lp;
        }
    }
}

// ---------------------------------------------------------------------------
// Attention via mma.sync m16n8k16 bf16 (3-way hi/lo split), single-pass
// softmax with mask bias as C-initializer. (unchanged from R14 win)
// ---------------------------------------------------------------------------
#define ST_KHI  0
#define ST_KLO  3072
#define ST_VTHI 6144
#define ST_VTLO 8448
#define ST_MB   10752
#define ST_SZ   11008

__global__ void __launch_bounds__(256) attn_kernel() {
    __shared__ __align__(16) char sm[2*ST_SZ];
    u32 smb = smem_u32(sm);

    int bh  = blockIdx.x;
    int b   = bh >> 2;
    int h   = bh & 3;
    int qt  = blockIdx.y;
    int tid = threadIdx.x;
    int w    = tid >> 5;
    int lane = tid & 31;
    int g    = lane >> 2;
    int t    = lane & 3;

    int qrow = qt*128 + w*16 + g;
    const __nv_bfloat16* Qh = g_Qh + (u64)bh*1024*16;
    const __nv_bfloat16* Ql = g_Ql + (u64)bh*1024*16;
    u32 qh0 = *(const u32*)(Qh + qrow*16     + 2*t);
    u32 qh1 = *(const u32*)(Qh + (qrow+8)*16 + 2*t);
    u32 qh2 = *(const u32*)(Qh + qrow*16     + 2*t + 8);
    u32 qh3 = *(const u32*)(Qh + (qrow+8)*16 + 2*t + 8);
    u32 ql0 = *(const u32*)(Ql + qrow*16     + 2*t);
    u32 ql1 = *(const u32*)(Ql + (qrow+8)*16 + 2*t);
    u32 ql2 = *(const u32*)(Ql + qrow*16     + 2*t + 8);
    u32 ql3 = *(const u32*)(Ql + (qrow+8)*16 + 2*t + 8);

    float ctx0[4] = {0,0,0,0}, ctx1[4] = {0,0,0,0};
    float lA = 0.0f, lB = 0.0f;

    const __nv_bfloat16* Khg  = g_Kh  + (u64)bh*1024*16;
    const __nv_bfloat16* Klg  = g_Kl  + (u64)bh*1024*16;
    const __nv_bfloat16* Vthg = g_Vth + (u64)bh*16*1024;
    const __nv_bfloat16* Vtlg = g_Vtl + (u64)bh*16*1024;
    const float* mbg = g_mb + b*1024;

    auto load_tile = [&](int kb, int stage) {
        u32 sb = smb + stage*ST_SZ;
        for (int j = tid; j < 528; j += 256) {
            if (j < 128) {
                int key = j >> 1, part = j & 1;
                cpasync16(sb + ST_KHI + key*48 + part*16,
                          Khg + (kb + key)*16 + part*8);
            } else if (j < 256) {
                int j2 = j - 128, key = j2 >> 1, part = j2 & 1;
                cpasync16(sb + ST_KLO + key*48 + part*16,
                          Klg + (kb + key)*16 + part*8);
            } else if (j < 384) {
                int j2 = j - 256, dd = j2 >> 3, part = j2 & 7;
                cpasync16(sb + ST_VTHI + dd*144 + part*16,
                          Vthg + dd*1024 + kb + part*8);
            } else if (j < 512) {
                int j2 = j - 384, dd = j2 >> 3, part = j2 & 7;
                cpasync16(sb + ST_VTLO + dd*144 + part*16,
                          Vtlg + dd*1024 + kb + part*8);
            } else {
                int m = j - 512;
                cpasync16(sb + ST_MB + m*16, mbg + kb + m*4);
            }
        }
        asm volatile("cp.async.commit_group;" ::: "memory");
    };

    load_tile(0, 0);

    for (int tile = 0; tile < 16; ++tile) {
        int s = tile & 1;
        if (tile < 15) {
            load_tile((tile+1)*64, s^1);
            asm volatile("cp.async.wait_group 1;" ::: "memory");
        } else {
            asm volatile("cp.async.wait_group 0;" ::: "memory");
        }
        __syncthreads();

        const char* st = sm + s*ST_SZ;

#pragma unroll
        for (int c4 = 0; c4 < 4; ++c4) {
            int cb = c4*16;
            const char* k0p = st + ST_KHI + (cb+g)*48   + t*4;
            const char* k1p = st + ST_KHI + (cb+8+g)*48 + t*4;
            u32 kh0a = *(const u32*)k0p,        kh0b = *(const u32*)(k0p+16);
            u32 kh1a = *(const u32*)k1p,        kh1b = *(const u32*)(k1p+16);
            const char* l0p = st + ST_KLO + (cb+g)*48   + t*4;
            const char* l1p = st + ST_KLO + (cb+8+g)*48 + t*4;
            u32 kl0a = *(const u32*)l0p,        kl0b = *(const u32*)(l0p+16);
            u32 kl1a = *(const u32*)l1p,        kl1b = *(const u32*)(l1p+16);

            float2 mbv0 = *(const float2*)(st + ST_MB + (cb + 2*t)*4);
            float2 mbv1 = *(const float2*)(st + ST_MB + (cb + 8 + 2*t)*4);

            float s00 = mbv0.x, s01 = mbv0.y, s02 = mbv0.x, s03 = mbv0.y;
            mma16816(s00,s01,s02,s03, qh0,qh1,qh2,qh3, kh0a,kh0b);
            mma16816(s00,s01,s02,s03, qh0,qh1,qh2,qh3, kl0a,kl0b);
            mma16816(s00,s01,s02,s03, ql0,ql1,ql2,ql3, kh0a,kh0b);
            float s10 = mbv1.x, s11 = mbv1.y, s12 = mbv1.x, s13 = mbv1.y;
            mma16816(s10,s11,s12,s13, qh0,qh1,qh2,qh3, kh1a,kh1b);
            mma16816(s10,s11,s12,s13, qh0,qh1,qh2,qh3, kl1a,kl1b);
            mma16816(s10,s11,s12,s13, ql0,ql1,ql2,ql3, kh1a,kh1b);

            float p00 = ex2a(s00), p01 = ex2a(s01), p02 = ex2a(s02), p03 = ex2a(s03);
            float p10 = ex2a(s10), p11 = ex2a(s11), p12 = ex2a(s12), p13 = ex2a(s13);
            lA += p00 + p01 + p10 + p11;
            lB += p02 + p03 + p12 + p13;

            u32 ph0 = pkbf(p00, p01), ph1 = pkbf(p02, p03);
            u32 ph2 = pkbf(p10, p11), ph3 = pkbf(p12, p13);
            float q00 = p00 - __uint_as_float(ph0 << 16);
            float q01 = p01 - __uint_as_float(ph0 & 0xffff0000u);
            float q02 = p02 - __uint_as_float(ph1 << 16);
            float q03 = p03 - __uint_as_float(ph1 & 0xffff0000u);
            float q10 = p10 - __uint_as_float(ph2 << 16);
            float q11 = p11 - __uint_as_float(ph2 & 0xffff0000u);
            float q12 = p12 - __uint_as_float(ph3 << 16);
            float q13 = p13 - __uint_as_float(ph3 & 0xffff0000u);
            u32 pl0 = pkbf(q00, q01), pl1 = pkbf(q02, q03);
            u32 pl2 = pkbf(q10, q11), pl3 = pkbf(q12, q13);

            const char* v0p = st + ST_VTHI + g*144     + (cb + 2*t)*2;
            const char* v1p = st + ST_VTHI + (8+g)*144 + (cb + 2*t)*2;
            u32 vh0a = *(const u32*)v0p,        vh0b = *(const u32*)(v0p+16);
            u32 vh1a = *(const u32*)v1p,        vh1b = *(const u32*)(v1p+16);
            const char* w0p = st + ST_VTLO + g*144     + (cb + 2*t)*2;
            const char* w1p = st + ST_VTLO + (8+g)*144 + (cb + 2*t)*2;
            u32 vl0a = *(const u32*)w0p,        vl0b = *(const u32*)(w0p+16);
            u32 vl1a = *(const u32*)w1p,        vl1b = *(const u32*)(w1p+16);

            mma16816(ctx0[0],ctx0[1],ctx0[2],ctx0[3], ph0,ph1,ph2,ph3, vh0a,vh0b);
            mma16816(ctx0[0],ctx0[1],ctx0[2],ctx0[3], ph0,ph1,ph2,ph3, vl0a,vl0b);
            mma16816(ctx0[0],ctx0[1],ctx0[2],ctx0[3], pl0,pl1,pl2,pl3, vh0a,vh0b);
            mma16816(ctx1[0],ctx1[1],ctx1[2],ctx1[3], ph0,ph1,ph2,ph3, vh1a,vh1b);
            mma16816(ctx1[0],ctx1[1],ctx1[2],ctx1[3], ph0,ph1,ph2,ph3, vl1a,vl1b);
            mma16816(ctx1[0],ctx1[1],ctx1[2],ctx1[3], pl0,pl1,pl2,pl3, vh1a,vh1b);
        }
        __syncthreads();
    }

    lA += __shfl_xor_sync(0xffffffffu, lA, 1);
    lA += __shfl_xor_sync(0xffffffffu, lA, 2);
    lB += __shfl_xor_sync(0xffffffffu, lB, 1);
    lB += __shfl_xor_sync(0xffffffffu, lB, 2);
    float invA = 1.0f / lA;
    float invB = 1.0f / lB;

    int rowA = qt*128 + w*16 + g;
    int rowB = rowA + 8;
    float* outA = g_ctx + ((u64)b*1024 + rowA)*64 + h*16;
    float* outB = g_ctx + ((u64)b*1024 + rowB)*64 + h*16;
    *(float2*)(outA + 2*t)     = make_float2(ctx0[0]*invA, ctx0[1]*invA);
    *(float2*)(outA + 2*t + 8) = make_float2(ctx1[0]*invA, ctx1[1]*invA);
    *(float2*)(outB + 2*t)     = make_float2(ctx0[2]*invB, ctx0[3]*invB);
    *(float2*)(outB + 2*t + 8) = make_float2(ctx1[2]*invB, ctx1[3]*invB);
}

// ---------------------------------------------------------------------------
// Output projection, 64 rows/block.
// ---------------------------------------------------------------------------
__global__ void __launch_bounds__(256) proj_kernel(const float* __restrict__ Wp,
                                                   const float* __restrict__ bp,
                                                   float* __restrict__ out) {
    __shared__ float Xs[64][64];
    __shared__ float Ws[64][64];
    int rowbase = blockIdx.x * 64;

    for (int i = threadIdx.x; i < 64*64/4; i += 256) {
        ((float4*)Ws)[i] = ((const float4*)Wp)[i];
        ((float4*)Xs)[i] = ((const float4*)g_ctx)[rowbase*16 + i];
    }
    __syncthreads();

    int c  = threadIdx.x & 63;
    int rg = threadIdx.x >> 6;
    float bias = bp[c];
    float acc[16];
#pragma unroll
    for (int r = 0; r < 16; r++) acc[r] = bias;
#pragma unroll 4
    for (int k0 = 0; k0 < 64; k0 += 4) {
        float w0 = Ws[k0][c], w1 = Ws[k0+1][c], w2 = Ws[k0+2][c], w3 = Ws[k0+3][c];
#pragma unroll
        for (int r = 0; r < 16; r++) {
            float4 xv = *(const float4*)&Xs[rg*16 + r][k0];
            acc[r] += xv.x*w0 + xv.y*w1 + xv.z*w2 + xv.w*w3;
        }
    }
#pragma unroll
    for (int r = 0; r < 16; r++)
        out[(rowbase + rg*16 + r) * 64 + c] = acc[r];
}

// ---------------------------------------------------------------------------
extern "C" void kernel_launch(void* const* d_in, const int* in_sizes, int n_in,
                              void* d_out, int out_size) {
    const float* x    = (const float*)d_in[0];
    const float* enc  = (const float*)d_in[1];
    const int*   msk  = (const int*)  d_in[2];
    const float* Wkv  = (const float*)d_in[3];
    const float* bkv  = (const float*)d_in[4];
    const float* Wq   = (const float*)d_in[5];
    const float* bq   = (const float*)d_in[6];
    const float* Wp   = (const float*)d_in[7];
    const float* bp   = (const float*)d_in[8];
    float* out = (float*)d_out;

    qkv_kernel<<<1024, 256>>>(x, enc, msk, Wkv, bkv, Wq, bq);
    attn_kernel<<<dim3(BB*NH, TT/128), 256>>>();
    proj_kernel<<<ROWS_TOTAL/64, 256>>>(Wp, bp, out);
}

// round 16
// speedup vs baseline: 1.7765x; 1.0402x over previous
#include <cuda_runtime.h>
#include <cuda_bf16.h>
#include <cstdint>

#define DM 64
#define NH 4
#define BB 16
#define TT 1024
#define ROWS_TOTAL (BB*TT)
#define HEADROWS (ROWS_TOTAL*4)      // 64 bh x 1024 t

typedef unsigned long long u64;
typedef unsigned int u32;

__device__ __align__(16) __nv_bfloat16 g_Kh[HEADROWS*16];   // [bh][t][d]
__device__ __align__(16) __nv_bfloat16 g_Kl[HEADROWS*16];
__device__ __align__(16) __nv_bfloat16 g_Vth[HEADROWS*16];  // [bh][d][t]
__device__ __align__(16) __nv_bfloat16 g_Vtl[HEADROWS*16];
__device__ __align__(16) __nv_bfloat16 g_Qh[HEADROWS*16];   // [bh][t][d], pre-scaled
__device__ __align__(16) __nv_bfloat16 g_Ql[HEADROWS*16];
__device__ __align__(16) __nv_bfloat16 g_Wph[DM*DM];        // Wproj^T [n][k] hi
__device__ __align__(16) __nv_bfloat16 g_Wpl[DM*DM];        // Wproj^T [n][k] lo
__device__ __align__(16) float g_mb[BB*TT];
__device__ __align__(16) float g_ctx[ROWS_TOTAL*DM];        // [b,t,64]

// ---- helpers ----
__device__ __forceinline__ float ex2a(float x) {
    float y; asm("ex2.approx.f32 %0,%1;" : "=f"(y) : "f"(x)); return y;
}
__device__ __forceinline__ u32 smem_u32(const void* p) {
    u32 a;
    asm("{ .reg .u64 t; cvta.to.shared.u64 t, %1; cvt.u32.u64 %0, t; }"
        : "=r"(a) : "l"(p));
    return a;
}
__device__ __forceinline__ void cpasync16(u32 smem, const void* g) {
    u64 ga;
    asm("cvta.to.global.u64 %0, %1;" : "=l"(ga) : "l"(g));
    asm volatile("cp.async.ca.shared.global [%0], [%1], 16;"
                 :: "r"(smem), "l"(ga) : "memory");
}
__device__ __forceinline__ u32 pkbf(float lo, float hi) {
    u32 d;
    asm("cvt.rn.bf16x2.f32 %0, %1, %2;" : "=r"(d) : "f"(hi), "f"(lo));
    return d;
}
__device__ __forceinline__ void split_pair(float v0, float v1, u32& hp, u32& lp) {
    hp = pkbf(v0, v1);
    float l0 = v0 - __uint_as_float(hp << 16);
    float l1 = v1 - __uint_as_float(hp & 0xffff0000u);
    lp = pkbf(l0, l1);
}
__device__ __forceinline__ void mma16816(float& c0, float& c1, float& c2, float& c3,
                                         u32 a0, u32 a1, u32 a2, u32 a3,
                                         u32 b0, u32 b1) {
    asm("mma.sync.aligned.m16n8k16.row.col.f32.bf16.bf16.f32 "
        "{%0,%1,%2,%3}, {%4,%5,%6,%7}, {%8,%9}, {%0,%1,%2,%3};"
        : "+f"(c0), "+f"(c1), "+f"(c2), "+f"(c3)
        : "r"(a0), "r"(a1), "r"(a2), "r"(a3), "r"(b0), "r"(b1));
}

// ---------------------------------------------------------------------------
// Merged KV + Q projections -> bf16 hi/lo, u32-packed stores.
// Blocks [0,512): kv. Blocks [512,1024): q. Blocks 512..519 also convert
// Wproj into g_Wph/g_Wpl (transposed [n][k]); proj_kernel launches after.
// ---------------------------------------------------------------------------
__global__ void __launch_bounds__(256) qkv_kernel(const float* __restrict__ x,
                                                  const float* __restrict__ enc,
                                                  const int*   __restrict__ mask,
                                                  const float* __restrict__ Wkv,
                                                  const float* __restrict__ bkv,
                                                  const float* __restrict__ Wq,
                                                  const float* __restrict__ bq,
                                                  const float* __restrict__ Wp) {
    __shared__ float smem[32*64 + 64*128];
    float (*Xs)[64]  = (float(*)[64])smem;
    float (*Ws)[128] = (float(*)[128])(smem + 32*64);
    float (*Wsq)[64] = (float(*)[64])(smem + 32*64);

    {
        int gid = blockIdx.x*256 + threadIdx.x;
        if (gid < BB*TT) g_mb[gid] = mask[gid] ? 0.0f : -1e30f;
    }
    // Wproj^T bf16 conversion by blocks 512..519 (2048 threads, 1 k-pair each)
    if (blockIdx.x >= 512 && blockIdx.x < 520) {
        int p = (blockIdx.x - 512)*256 + threadIdx.x;   // 0..2047
        int n = p >> 5;
        int k0 = (p & 31) * 2;
        u32 hp, lp;
        split_pair(Wp[k0*64 + n], Wp[(k0+1)*64 + n], hp, lp);
        *(u32*)&g_Wph[n*64 + k0] = hp;
        *(u32*)&g_Wpl[n*64 + k0] = lp;
    }

    if (blockIdx.x < 512) {
        int rowbase = blockIdx.x * 32;
        for (int i = threadIdx.x; i < 64*128/4; i += 256)
            ((float4*)Ws)[i] = ((const float4*)Wkv)[i];
        for (int i = threadIdx.x; i < 32*64/4; i += 256)
            ((float4*)Xs)[i] = ((const float4*)enc)[rowbase*16 + i];
        __syncthreads();

        int pr = threadIdx.x & 63;
        int rg = threadIdx.x >> 6;
        int c0 = 2*pr;
        float2 bias = *(const float2*)&bkv[c0];
        float acc0[8], acc1[8];
#pragma unroll
        for (int r = 0; r < 8; r++) { acc0[r] = bias.x; acc1[r] = bias.y; }

#pragma unroll 4
        for (int k0 = 0; k0 < 64; k0 += 4) {
            float2 wA = *(const float2*)&Ws[k0  ][c0];
            float2 wB = *(const float2*)&Ws[k0+1][c0];
            float2 wC = *(const float2*)&Ws[k0+2][c0];
            float2 wD = *(const float2*)&Ws[k0+3][c0];
#pragma unroll
            for (int r = 0; r < 8; r++) {
                float4 xv = *(const float4*)&Xs[rg*8 + r][k0];
                acc0[r] += xv.x*wA.x + xv.y*wB.x + xv.z*wC.x + xv.w*wD.x;
                acc1[r] += xv.x*wA.y + xv.y*wB.y + xv.z*wC.y + xv.w*wD.y;
            }
        }

        int h = (c0 >> 4) & 3;
        int d = c0 & 15;
        if (pr < 32) {
#pragma unroll
            for (int r = 0; r < 8; r++) {
                int row = rowbase + rg*8 + r;
                int b = row >> 10, tt = row & 1023;
                int idx = ((((b << 2) | h) * 1024 + tt) * 16 + d);
                u32 hp, lp;
                split_pair(acc0[r], acc1[r], hp, lp);
                *(u32*)&g_Kh[idx] = hp;
                *(u32*)&g_Kl[idx] = lp;
            }
        } else {
#pragma unroll
            for (int r = 0; r < 8; r += 2) {
                int row = rowbase + rg*8 + r;
                int b = row >> 10, tt = row & 1023;
                int bh = (b << 2) | h;
                u32 hp0, lp0, hp1, lp1;
                split_pair(acc0[r], acc0[r+1], hp0, lp0);
                split_pair(acc1[r], acc1[r+1], hp1, lp1);
                int i0 = (bh * 16 + d)     * 1024 + tt;
                int i1 = (bh * 16 + d + 1) * 1024 + tt;
                *(u32*)&g_Vth[i0] = hp0; *(u32*)&g_Vtl[i0] = lp0;
                *(u32*)&g_Vth[i1] = hp1; *(u32*)&g_Vtl[i1] = lp1;
            }
        }
    } else {
        const float QS = 0.25f * 1.4426950408889634f;
        int rowbase = (blockIdx.x - 512) * 32;
        for (int i = threadIdx.x; i < 64*64/4; i += 256)
            ((float4*)Wsq)[i] = ((const float4*)Wq)[i];
        for (int i = threadIdx.x; i < 32*64/4; i += 256)
            ((float4*)Xs)[i]  = ((const float4*)x)[rowbase*16 + i];
        __syncthreads();

        int pr = threadIdx.x & 31;
        int rg = threadIdx.x >> 5;
        int c0 = 2*pr;
        float2 bias = *(const float2*)&bq[c0];
        float acc0[4], acc1[4];
#pragma unroll
        for (int r = 0; r < 4; r++) { acc0[r] = bias.x; acc1[r] = bias.y; }

#pragma unroll 4
        for (int k0 = 0; k0 < 64; k0 += 4) {
            float2 wA = *(const float2*)&Wsq[k0  ][c0];
            float2 wB = *(const float2*)&Wsq[k0+1][c0];
            float2 wC = *(const float2*)&Wsq[k0+2][c0];
            float2 wD = *(const float2*)&Wsq[k0+3][c0];
#pragma unroll
            for (int r = 0; r < 4; r++) {
                float4 xv = *(const float4*)&Xs[rg*4 + r][k0];
                acc0[r] += xv.x*wA.x + xv.y*wB.x + xv.z*wC.x + xv.w*wD.x;
                acc1[r] += xv.x*wA.y + xv.y*wB.y + xv.z*wC.y + xv.w*wD.y;
            }
        }

        int h = c0 >> 4;
        int d = c0 & 15;
#pragma unroll
        for (int r = 0; r < 4; r++) {
            int row = rowbase + rg*4 + r;
            int b = row >> 10, tt = row & 1023;
            int idx = ((((b << 2) | h) * 1024 + tt) * 16 + d);
            u32 hp, lp;
            split_pair(acc0[r] * QS, acc1[r] * QS, hp, lp);
            *(u32*)&g_Qh[idx] = hp;
            *(u32*)&g_Ql[idx] = lp;
        }
    }
}

// ---------------------------------------------------------------------------
// Attention via mma.sync, 128-key double-buffered tiles.
// grid (64 bh, 8 qtile), block 256 = 8 warps; warp w owns 16 q-rows.
// Stage (21504 B): Khi@0 [128][48], Klo@6144, Vthi@12288 [16][272],
// Vtlo@16640, mb@20992 [128]f32.
// ---------------------------------------------------------------------------
#define ST_KHI  0
#define ST_KLO  6144
#define ST_VTHI 12288
#define ST_VTLO 16640
#define ST_MB   20992
#define ST_SZ   21504

__global__ void __launch_bounds__(256) attn_kernel() {
    __shared__ __align__(16) char sm[2*ST_SZ];
    u32 smb = smem_u32(sm);

    int bh  = blockIdx.x;
    int b   = bh >> 2;
    int h   = bh & 3;
    int qt  = blockIdx.y;
    int tid = threadIdx.x;
    int w    = tid >> 5;
    int lane = tid & 31;
    int g    = lane >> 2;
    int t    = lane & 3;

    int qrow = qt*128 + w*16 + g;
    const __nv_bfloat16* Qh = g_Qh + (u64)bh*1024*16;
    const __nv_bfloat16* Ql = g_Ql + (u64)bh*1024*16;
    u32 qh0 = *(const u32*)(Qh + qrow*16     + 2*t);
    u32 qh1 = *(const u32*)(Qh + (qrow+8)*16 + 2*t);
    u32 qh2 = *(const u32*)(Qh + qrow*16     + 2*t + 8);
    u32 qh3 = *(const u32*)(Qh + (qrow+8)*16 + 2*t + 8);
    u32 ql0 = *(const u32*)(Ql + qrow*16     + 2*t);
    u32 ql1 = *(const u32*)(Ql + (qrow+8)*16 + 2*t);
    u32 ql2 = *(const u32*)(Ql + qrow*16     + 2*t + 8);
    u32 ql3 = *(const u32*)(Ql + (qrow+8)*16 + 2*t + 8);

    float ctx0[4] = {0,0,0,0}, ctx1[4] = {0,0,0,0};
    float lA = 0.0f, lB = 0.0f;

    const __nv_bfloat16* Khg  = g_Kh  + (u64)bh*1024*16;
    const __nv_bfloat16* Klg  = g_Kl  + (u64)bh*1024*16;
    const __nv_bfloat16* Vthg = g_Vth + (u64)bh*16*1024;
    const __nv_bfloat16* Vtlg = g_Vtl + (u64)bh*16*1024;
    const float* mbg = g_mb + b*1024;

    // 128-key tile loader: 1056 16B jobs
    auto load_tile = [&](int kb, int stage) {
        u32 sb = smb + stage*ST_SZ;
        for (int j = tid; j < 1056; j += 256) {
            if (j < 256) {
                int key = j >> 1, part = j & 1;
                cpasync16(sb + ST_KHI + key*48 + part*16,
                          Khg + (kb + key)*16 + part*8);
            } else if (j < 512) {
                int j2 = j - 256, key = j2 >> 1, part = j2 & 1;
                cpasync16(sb + ST_KLO + key*48 + part*16,
                          Klg + (kb + key)*16 + part*8);
            } else if (j < 768) {
                int j2 = j - 512, dd = j2 >> 4, part = j2 & 15;
                cpasync16(sb + ST_VTHI + dd*272 + part*16,
                          Vthg + dd*1024 + kb + part*8);
            } else if (j < 1024) {
                int j2 = j - 768, dd = j2 >> 4, part = j2 & 15;
                cpasync16(sb + ST_VTLO + dd*272 + part*16,
                          Vtlg + dd*1024 + kb + part*8);
            } else {
                int m = j - 1024;
                cpasync16(sb + ST_MB + m*16, mbg + kb + m*4);
            }
        }
        asm volatile("cp.async.commit_group;" ::: "memory");
    };

    load_tile(0, 0);

    for (int tile = 0; tile < 8; ++tile) {
        int s = tile & 1;
        if (tile < 7) {
            load_tile((tile+1)*128, s^1);
            asm volatile("cp.async.wait_group 1;" ::: "memory");
        } else {
            asm volatile("cp.async.wait_group 0;" ::: "memory");
        }
        __syncthreads();

        const char* st = sm + s*ST_SZ;

#pragma unroll
        for (int c4 = 0; c4 < 8; ++c4) {
            int cb = c4*16;
            const char* k0p = st + ST_KHI + (cb+g)*48   + t*4;
            const char* k1p = st + ST_KHI + (cb+8+g)*48 + t*4;
            u32 kh0a = *(const u32*)k0p,        kh0b = *(const u32*)(k0p+16);
            u32 kh1a = *(const u32*)k1p,        kh1b = *(const u32*)(k1p+16);
            const char* l0p = st + ST_KLO + (cb+g)*48   + t*4;
            const char* l1p = st + ST_KLO + (cb+8+g)*48 + t*4;
            u32 kl0a = *(const u32*)l0p,        kl0b = *(const u32*)(l0p+16);
            u32 kl1a = *(const u32*)l1p,        kl1b = *(const u32*)(l1p+16);

            float2 mbv0 = *(const float2*)(st + ST_MB + (cb + 2*t)*4);
            float2 mbv1 = *(const float2*)(st + ST_MB + (cb + 8 + 2*t)*4);

            float s00 = mbv0.x, s01 = mbv0.y, s02 = mbv0.x, s03 = mbv0.y;
            mma16816(s00,s01,s02,s03, qh0,qh1,qh2,qh3, kh0a,kh0b);
            mma16816(s00,s01,s02,s03, qh0,qh1,qh2,qh3, kl0a,kl0b);
            mma16816(s00,s01,s02,s03, ql0,ql1,ql2,ql3, kh0a,kh0b);
            float s10 = mbv1.x, s11 = mbv1.y, s12 = mbv1.x, s13 = mbv1.y;
            mma16816(s10,s11,s12,s13, qh0,qh1,qh2,qh3, kh1a,kh1b);
            mma16816(s10,s11,s12,s13, qh0,qh1,qh2,qh3, kl1a,kl1b);
            mma16816(s10,s11,s12,s13, ql0,ql1,ql2,ql3, kh1a,kh1b);

            float p00 = ex2a(s00), p01 = ex2a(s01), p02 = ex2a(s02), p03 = ex2a(s03);
            float p10 = ex2a(s10), p11 = ex2a(s11), p12 = ex2a(s12), p13 = ex2a(s13);
            lA += p00 + p01 + p10 + p11;
            lB += p02 + p03 + p12 + p13;

            u32 ph0 = pkbf(p00, p01), ph1 = pkbf(p02, p03);
            u32 ph2 = pkbf(p10, p11), ph3 = pkbf(p12, p13);
            float q00 = p00 - __uint_as_float(ph0 << 16);
            float q01 = p01 - __uint_as_float(ph0 & 0xffff0000u);
            float q02 = p02 - __uint_as_float(ph1 << 16);
            float q03 = p03 - __uint_as_float(ph1 & 0xffff0000u);
            float q10 = p10 - __uint_as_float(ph2 << 16);
            float q11 = p11 - __uint_as_float(ph2 & 0xffff0000u);
            float q12 = p12 - __uint_as_float(ph3 << 16);
            float q13 = p13 - __uint_as_float(ph3 & 0xffff0000u);
            u32 pl0 = pkbf(q00, q01), pl1 = pkbf(q02, q03);
            u32 pl2 = pkbf(q10, q11), pl3 = pkbf(q12, q13);

            const char* v0p = st + ST_VTHI + g*272     + (cb + 2*t)*2;
            const char* v1p = st + ST_VTHI + (8+g)*272 + (cb + 2*t)*2;
            u32 vh0a = *(const u32*)v0p,        vh0b = *(const u32*)(v0p+16);
            u32 vh1a = *(const u32*)v1p,        vh1b = *(const u32*)(v1p+16);
            const char* w0p = st + ST_VTLO + g*272     + (cb + 2*t)*2;
            const char* w1p = st + ST_VTLO + (8+g)*272 + (cb + 2*t)*2;
            u32 vl0a = *(const u32*)w0p,        vl0b = *(const u32*)(w0p+16);
            u32 vl1a = *(const u32*)w1p,        vl1b = *(const u32*)(w1p+16);

            mma16816(ctx0[0],ctx0[1],ctx0[2],ctx0[3], ph0,ph1,ph2,ph3, vh0a,vh0b);
            mma16816(ctx0[0],ctx0[1],ctx0[2],ctx0[3], ph0,ph1,ph2,ph3, vl0a,vl0b);
            mma16816(ctx0[0],ctx0[1],ctx0[2],ctx0[3], pl0,pl1,pl2,pl3, vh0a,vh0b);
            mma16816(ctx1[0],ctx1[1],ctx1[2],ctx1[3], ph0,ph1,ph2,ph3, vh1a,vh1b);
            mma16816(ctx1[0],ctx1[1],ctx1[2],ctx1[3], ph0,ph1,ph2,ph3, vl1a,vl1b);
            mma16816(ctx1[0],ctx1[1],ctx1[2],ctx1[3], pl0,pl1,pl2,pl3, vh1a,vh1b);
        }
        __syncthreads();
    }

    lA += __shfl_xor_sync(0xffffffffu, lA, 1);
    lA += __shfl_xor_sync(0xffffffffu, lA, 2);
    lB += __shfl_xor_sync(0xffffffffu, lB, 1);
    lB += __shfl_xor_sync(0xffffffffu, lB, 2);
    float invA = 1.0f / lA;
    float invB = 1.0f / lB;

    int rowA = qt*128 + w*16 + g;
    int rowB = rowA + 8;
    float* outA = g_ctx + ((u64)b*1024 + rowA)*64 + h*16;
    float* outB = g_ctx + ((u64)b*1024 + rowB)*64 + h*16;
    *(float2*)(outA + 2*t)     = make_float2(ctx0[0]*invA, ctx0[1]*invA);
    *(float2*)(outA + 2*t + 8) = make_float2(ctx1[0]*invA, ctx1[1]*invA);
    *(float2*)(outB + 2*t)     = make_float2(ctx0[2]*invB, ctx0[3]*invB);
    *(float2*)(outB + 2*t + 8) = make_float2(ctx1[2]*invB, ctx1[3]*invB);
}

// ---------------------------------------------------------------------------
// Output projection via mma.sync: out = ctx @ Wp + bp.
// Block 128 = 4 warps; warp w owns rows blk*64 + w*16 + (g, g+8). 8 n-tiles.
// A from f32 ctx (split in regs); B from g_Wph/g_Wpl (L1-hot, 8KB each).
// ---------------------------------------------------------------------------
__global__ void __launch_bounds__(128) proj_kernel(const float* __restrict__ bp,
                                                   float* __restrict__ out) {
    int tid = threadIdx.x;
    int w    = tid >> 5;
    int lane = tid & 31;
    int g    = lane >> 2;
    int t    = lane & 3;

    int rowA = blockIdx.x*64 + w*16 + g;
    int rowB = rowA + 8;

    float acc[8][4];
#pragma unroll
    for (int nn = 0; nn < 8; nn++) {
        float2 bb = *(const float2*)&bp[nn*8 + 2*t];
        acc[nn][0] = bb.x; acc[nn][1] = bb.y;
        acc[nn][2] = bb.x; acc[nn][3] = bb.y;
    }

    const float* cA = g_ctx + (u64)rowA*64;
    const float* cB = g_ctx + (u64)rowB*64;

#pragma unroll
    for (int kk = 0; kk < 4; kk++) {
        int kb = kk*16;
        float2 x0 = *(const float2*)&cA[kb + 2*t];
        float2 x1 = *(const float2*)&cB[kb + 2*t];
        float2 x2 = *(const float2*)&cA[kb + 2*t + 8];
        float2 x3 = *(const float2*)&cB[kb + 2*t + 8];
        u32 ah0, al0, ah1, al1, ah2, al2, ah3, al3;
        split_pair(x0.x, x0.y, ah0, al0);
        split_pair(x1.x, x1.y, ah1, al1);
        split_pair(x2.x, x2.y, ah2, al2);
        split_pair(x3.x, x3.y, ah3, al3);

#pragma unroll
        for (int nn = 0; nn < 8; nn++) {
            int n = nn*8 + g;
            u32 bh0 = *(const u32*)&g_Wph[n*64 + kb + 2*t];
            u32 bh1 = *(const u32*)&g_Wph[n*64 + kb + 2*t + 8];
            u32 bl0 = *(const u32*)&g_Wpl[n*64 + kb + 2*t];
            u32 bl1 = *(const u32*)&g_Wpl[n*64 + kb + 2*t + 8];
            mma16816(acc[nn][0], acc[nn][1], acc[nn][2], acc[nn][3],
                     ah0, ah1, ah2, ah3, bh0, bh1);
            mma16816(acc[nn][0], acc[nn][1], acc[nn][2], acc[nn][3],
                     ah0, ah1, ah2, ah3, bl0, bl1);
            mma16816(acc[nn][0], acc[nn][1], acc[nn][2], acc[nn][3],
                     al0, al1, al2, al3, bh0, bh1);
        }
    }

#pragma unroll
    for (int nn = 0; nn < 8; nn++) {
        *(float2*)&out[(u64)rowA*64 + nn*8 + 2*t] = make_float2(acc[nn][0], acc[nn][1]);
        *(float2*)&out[(u64)rowB*64 + nn*8 + 2*t] = make_float2(acc[nn][2], acc[nn][3]);
    }
}

// ---------------------------------------------------------------------------
extern "C" void kernel_launch(void* const* d_in, const int* in_sizes, int n_in,
                              void* d_out, int out_size) {
    const float* x    = (const float*)d_in[0];
    const float* enc  = (const float*)d_in[1];
    const int*   msk  = (const int*)  d_in[2];
    const float* Wkv  = (const float*)d_in[3];
    const float* bkv  = (const float*)d_in[4];
    const float* Wq   = (const float*)d_in[5];
    const float* bq   = (const float*)d_in[6];
    const float* Wp   = (const float*)d_in[7];
    const float* bp   = (const float*)d_in[8];
    float* out = (float*)d_out;

    qkv_kernel<<<1024, 256>>>(x, enc, msk, Wkv, bkv, Wq, bq, Wp);
    attn_kernel<<<dim3(BB*NH, TT/128), 256>>>();
    proj_kernel<<<ROWS_TOTAL/64, 128>>>(bp, out);
}

// round 17
// speedup vs baseline: 2.2642x; 1.2746x over previous
#include <cuda_runtime.h>
#include <cuda_bf16.h>
#include <cstdint>

#define DM 64
#define NH 4
#define BB 16
#define TT 1024
#define ROWS_TOTAL (BB*TT)
#define HEADROWS (ROWS_TOTAL*4)      // 64 bh x 1024 t

typedef unsigned long long u64;
typedef unsigned int u32;

__device__ __align__(16) __nv_bfloat16 g_Kh[HEADROWS*16];   // [bh][t][d]
__device__ __align__(16) __nv_bfloat16 g_Kl[HEADROWS*16];
__device__ __align__(16) __nv_bfloat16 g_Vth[HEADROWS*16];  // [bh][d][t]
__device__ __align__(16) __nv_bfloat16 g_Qh[HEADROWS*16];   // [bh][t][d], pre-scaled
__device__ __align__(16) __nv_bfloat16 g_Ql[HEADROWS*16];
__device__ __align__(16) __nv_bfloat16 g_Wph[DM*DM];        // Wproj^T [n][k] hi
__device__ __align__(16) __nv_bfloat16 g_Wpl[DM*DM];        // Wproj^T [n][k] lo
__device__ __align__(16) float g_mb[BB*TT];
__device__ __align__(16) float g_ctx[ROWS_TOTAL*DM];        // [b,t,64]

// ---- helpers ----
__device__ __forceinline__ float ex2a(float x) {
    float y; asm("ex2.approx.f32 %0,%1;" : "=f"(y) : "f"(x)); return y;
}
__device__ __forceinline__ u32 smem_u32(const void* p) {
    u32 a;
    asm("{ .reg .u64 t; cvta.to.shared.u64 t, %1; cvt.u32.u64 %0, t; }"
        : "=r"(a) : "l"(p));
    return a;
}
__device__ __forceinline__ void cpasync16(u32 smem, const void* g) {
    u64 ga;
    asm("cvta.to.global.u64 %0, %1;" : "=l"(ga) : "l"(g));
    asm volatile("cp.async.ca.shared.global [%0], [%1], 16;"
                 :: "r"(smem), "l"(ga) : "memory");
}
__device__ __forceinline__ u32 pkbf(float lo, float hi) {
    u32 d;
    asm("cvt.rn.bf16x2.f32 %0, %1, %2;" : "=r"(d) : "f"(hi), "f"(lo));
    return d;
}
__device__ __forceinline__ void split_pair(float v0, float v1, u32& hp, u32& lp) {
    hp = pkbf(v0, v1);
    float l0 = v0 - __uint_as_float(hp << 16);
    float l1 = v1 - __uint_as_float(hp & 0xffff0000u);
    lp = pkbf(l0, l1);
}
__device__ __forceinline__ void mma16816(float& c0, float& c1, float& c2, float& c3,
                                         u32 a0, u32 a1, u32 a2, u32 a3,
                                         u32 b0, u32 b1) {
    asm("mma.sync.aligned.m16n8k16.row.col.f32.bf16.bf16.f32 "
        "{%0,%1,%2,%3}, {%4,%5,%6,%7}, {%8,%9}, {%0,%1,%2,%3};"
        : "+f"(c0), "+f"(c1), "+f"(c2), "+f"(c3)
        : "r"(a0), "r"(a1), "r"(a2), "r"(a3), "r"(b0), "r"(b1));
}

// ---------------------------------------------------------------------------
// Merged KV + Q projections -> bf16 (K/Q hi+lo, V hi only), u32-packed stores.
// Blocks [0,512): kv. Blocks [512,1024): q (512..519 also convert Wproj).
// ---------------------------------------------------------------------------
__global__ void __launch_bounds__(256) qkv_kernel(const float* __restrict__ x,
                                                  const float* __restrict__ enc,
                                                  const int*   __restrict__ mask,
                                                  const float* __restrict__ Wkv,
                                                  const float* __restrict__ bkv,
                                                  const float* __restrict__ Wq,
                                                  const float* __restrict__ bq,
                                                  const float* __restrict__ Wp) {
    __shared__ float smem[32*64 + 64*128];
    float (*Xs)[64]  = (float(*)[64])smem;
    float (*Ws)[128] = (float(*)[128])(smem + 32*64);
    float (*Wsq)[64] = (float(*)[64])(smem + 32*64);

    {
        int gid = blockIdx.x*256 + threadIdx.x;
        if (gid < BB*TT) g_mb[gid] = mask[gid] ? 0.0f : -1e30f;
    }
    if (blockIdx.x >= 512 && blockIdx.x < 520) {
        int p = (blockIdx.x - 512)*256 + threadIdx.x;   // 0..2047
        int n = p >> 5;
        int k0 = (p & 31) * 2;
        u32 hp, lp;
        split_pair(Wp[k0*64 + n], Wp[(k0+1)*64 + n], hp, lp);
        *(u32*)&g_Wph[n*64 + k0] = hp;
        *(u32*)&g_Wpl[n*64 + k0] = lp;
    }

    if (blockIdx.x < 512) {
        int rowbase = blockIdx.x * 32;
        for (int i = threadIdx.x; i < 64*128/4; i += 256)
            ((float4*)Ws)[i] = ((const float4*)Wkv)[i];
        for (int i = threadIdx.x; i < 32*64/4; i += 256)
            ((float4*)Xs)[i] = ((const float4*)enc)[rowbase*16 + i];
        __syncthreads();

        int pr = threadIdx.x & 63;
        int rg = threadIdx.x >> 6;
        int c0 = 2*pr;
        float2 bias = *(const float2*)&bkv[c0];
        float acc0[8], acc1[8];
#pragma unroll
        for (int r = 0; r < 8; r++) { acc0[r] = bias.x; acc1[r] = bias.y; }

#pragma unroll 4
        for (int k0 = 0; k0 < 64; k0 += 4) {
            float2 wA = *(const float2*)&Ws[k0  ][c0];
            float2 wB = *(const float2*)&Ws[k0+1][c0];
            float2 wC = *(const float2*)&Ws[k0+2][c0];
            float2 wD = *(const float2*)&Ws[k0+3][c0];
#pragma unroll
            for (int r = 0; r < 8; r++) {
                float4 xv = *(const float4*)&Xs[rg*8 + r][k0];
                acc0[r] += xv.x*wA.x + xv.y*wB.x + xv.z*wC.x + xv.w*wD.x;
                acc1[r] += xv.x*wA.y + xv.y*wB.y + xv.z*wC.y + xv.w*wD.y;
            }
        }

        int h = (c0 >> 4) & 3;
        int d = c0 & 15;
        if (pr < 32) {
#pragma unroll
            for (int r = 0; r < 8; r++) {
                int row = rowbase + rg*8 + r;
                int b = row >> 10, tt = row & 1023;
                int idx = ((((b << 2) | h) * 1024 + tt) * 16 + d);
                u32 hp, lp;
                split_pair(acc0[r], acc1[r], hp, lp);
                *(u32*)&g_Kh[idx] = hp;
                *(u32*)&g_Kl[idx] = lp;
            }
        } else {
            // V hi only
#pragma unroll
            for (int r = 0; r < 8; r += 2) {
                int row = rowbase + rg*8 + r;
                int b = row >> 10, tt = row & 1023;
                int bh = (b << 2) | h;
                u32 hp0 = pkbf(acc0[r], acc0[r+1]);
                u32 hp1 = pkbf(acc1[r], acc1[r+1]);
                int i0 = (bh * 16 + d)     * 1024 + tt;
                int i1 = (bh * 16 + d + 1) * 1024 + tt;
                *(u32*)&g_Vth[i0] = hp0;
                *(u32*)&g_Vth[i1] = hp1;
            }
        }
    } else {
        const float QS = 0.25f * 1.4426950408889634f;
        int rowbase = (blockIdx.x - 512) * 32;
        for (int i = threadIdx.x; i < 64*64/4; i += 256)
            ((float4*)Wsq)[i] = ((const float4*)Wq)[i];
        for (int i = threadIdx.x; i < 32*64/4; i += 256)
            ((float4*)Xs)[i]  = ((const float4*)x)[rowbase*16 + i];
        __syncthreads();

        int pr = threadIdx.x & 31;
        int rg = threadIdx.x >> 5;
        int c0 = 2*pr;
        float2 bias = *(const float2*)&bq[c0];
        float acc0[4], acc1[4];
#pragma unroll
        for (int r = 0; r < 4; r++) { acc0[r] = bias.x; acc1[r] = bias.y; }

#pragma unroll 4
        for (int k0 = 0; k0 < 64; k0 += 4) {
            float2 wA = *(const float2*)&Wsq[k0  ][c0];
            float2 wB = *(const float2*)&Wsq[k0+1][c0];
            float2 wC = *(const float2*)&Wsq[k0+2][c0];
            float2 wD = *(const float2*)&Wsq[k0+3][c0];
#pragma unroll
            for (int r = 0; r < 4; r++) {
                float4 xv = *(const float4*)&Xs[rg*4 + r][k0];
                acc0[r] += xv.x*wA.x + xv.y*wB.x + xv.z*wC.x + xv.w*wD.x;
                acc1[r] += xv.x*wA.y + xv.y*wB.y + xv.z*wC.y + xv.w*wD.y;
            }
        }

        int h = c0 >> 4;
        int d = c0 & 15;
#pragma unroll
        for (int r = 0; r < 4; r++) {
            int row = rowbase + rg*4 + r;
            int b = row >> 10, tt = row & 1023;
            int idx = ((((b << 2) | h) * 1024 + tt) * 16 + d);
            u32 hp, lp;
            split_pair(acc0[r] * QS, acc1[r] * QS, hp, lp);
            *(u32*)&g_Qh[idx] = hp;
            *(u32*)&g_Ql[idx] = lp;
        }
    }
}

// ---------------------------------------------------------------------------
// Attention via mma.sync, 128-key double-buffered tiles.
// S = Qhi*Khi + Qhi*Klo + Qlo*Khi (full 3-way); ctx = Phi*Vhi only
// (V-lo/P-lo second-order terms dropped; error ~1e-4 << 1e-3 gate).
// Stage (17152 B): Khi@0 [128][48], Klo@6144, Vthi@12288 [16][272], mb@16640.
// ---------------------------------------------------------------------------
#define ST_KHI  0
#define ST_KLO  6144
#define ST_VTHI 12288
#define ST_MB   16640
#define ST_SZ   17152

__global__ void __launch_bounds__(256) attn_kernel() {
    __shared__ __align__(16) char sm[2*ST_SZ];
    u32 smb = smem_u32(sm);

    int bh  = blockIdx.x;
    int b   = bh >> 2;
    int h   = bh & 3;
    int qt  = blockIdx.y;
    int tid = threadIdx.x;
    int w    = tid >> 5;
    int lane = tid & 31;
    int g    = lane >> 2;
    int t    = lane & 3;

    int qrow = qt*128 + w*16 + g;
    const __nv_bfloat16* Qh = g_Qh + (u64)bh*1024*16;
    const __nv_bfloat16* Ql = g_Ql + (u64)bh*1024*16;
    u32 qh0 = *(const u32*)(Qh + qrow*16     + 2*t);
    u32 qh1 = *(const u32*)(Qh + (qrow+8)*16 + 2*t);
    u32 qh2 = *(const u32*)(Qh + qrow*16     + 2*t + 8);
    u32 qh3 = *(const u32*)(Qh + (qrow+8)*16 + 2*t + 8);
    u32 ql0 = *(const u32*)(Ql + qrow*16     + 2*t);
    u32 ql1 = *(const u32*)(Ql + (qrow+8)*16 + 2*t);
    u32 ql2 = *(const u32*)(Ql + qrow*16     + 2*t + 8);
    u32 ql3 = *(const u32*)(Ql + (qrow+8)*16 + 2*t + 8);

    float ctx0[4] = {0,0,0,0}, ctx1[4] = {0,0,0,0};
    float lA = 0.0f, lB = 0.0f;

    const __nv_bfloat16* Khg  = g_Kh  + (u64)bh*1024*16;
    const __nv_bfloat16* Klg  = g_Kl  + (u64)bh*1024*16;
    const __nv_bfloat16* Vthg = g_Vth + (u64)bh*16*1024;
    const float* mbg = g_mb + b*1024;

    // 128-key tile loader: 800 16B jobs
    auto load_tile = [&](int kb, int stage) {
        u32 sb = smb + stage*ST_SZ;
        for (int j = tid; j < 800; j += 256) {
            if (j < 256) {
                int key = j >> 1, part = j & 1;
                cpasync16(sb + ST_KHI + key*48 + part*16,
                          Khg + (kb + key)*16 + part*8);
            } else if (j < 512) {
                int j2 = j - 256, key = j2 >> 1, part = j2 & 1;
                cpasync16(sb + ST_KLO + key*48 + part*16,
                          Klg + (kb + key)*16 + part*8);
            } else if (j < 768) {
                int j2 = j - 512, dd = j2 >> 4, part = j2 & 15;
                cpasync16(sb + ST_VTHI + dd*272 + part*16,
                          Vthg + dd*1024 + kb + part*8);
            } else {
                int m = j - 768;
                cpasync16(sb + ST_MB + m*16, mbg + kb + m*4);
            }
        }
        asm volatile("cp.async.commit_group;" ::: "memory");
    };

    load_tile(0, 0);

    for (int tile = 0; tile < 8; ++tile) {
        int s = tile & 1;
        if (tile < 7) {
            load_tile((tile+1)*128, s^1);
            asm volatile("cp.async.wait_group 1;" ::: "memory");
        } else {
            asm volatile("cp.async.wait_group 0;" ::: "memory");
        }
        __syncthreads();

        const char* st = sm + s*ST_SZ;

#pragma unroll
        for (int c4 = 0; c4 < 8; ++c4) {
            int cb = c4*16;
            const char* k0p = st + ST_KHI + (cb+g)*48   + t*4;
            const char* k1p = st + ST_KHI + (cb+8+g)*48 + t*4;
            u32 kh0a = *(const u32*)k0p,        kh0b = *(const u32*)(k0p+16);
            u32 kh1a = *(const u32*)k1p,        kh1b = *(const u32*)(k1p+16);
            const char* l0p = st + ST_KLO + (cb+g)*48   + t*4;
            const char* l1p = st + ST_KLO + (cb+8+g)*48 + t*4;
            u32 kl0a = *(const u32*)l0p,        kl0b = *(const u32*)(l0p+16);
            u32 kl1a = *(const u32*)l1p,        kl1b = *(const u32*)(l1p+16);

            float2 mbv0 = *(const float2*)(st + ST_MB + (cb + 2*t)*4);
            float2 mbv1 = *(const float2*)(st + ST_MB + (cb + 8 + 2*t)*4);

            float s00 = mbv0.x, s01 = mbv0.y, s02 = mbv0.x, s03 = mbv0.y;
            mma16816(s00,s01,s02,s03, qh0,qh1,qh2,qh3, kh0a,kh0b);
            mma16816(s00,s01,s02,s03, qh0,qh1,qh2,qh3, kl0a,kl0b);
            mma16816(s00,s01,s02,s03, ql0,ql1,ql2,ql3, kh0a,kh0b);
            float s10 = mbv1.x, s11 = mbv1.y, s12 = mbv1.x, s13 = mbv1.y;
            mma16816(s10,s11,s12,s13, qh0,qh1,qh2,qh3, kh1a,kh1b);
            mma16816(s10,s11,s12,s13, qh0,qh1,qh2,qh3, kl1a,kl1b);
            mma16816(s10,s11,s12,s13, ql0,ql1,ql2,ql3, kh1a,kh1b);

            float p00 = ex2a(s00), p01 = ex2a(s01), p02 = ex2a(s02), p03 = ex2a(s03);
            float p10 = ex2a(s10), p11 = ex2a(s11), p12 = ex2a(s12), p13 = ex2a(s13);
            lA += p00 + p01 + p10 + p11;
            lB += p02 + p03 + p12 + p13;

            u32 ph0 = pkbf(p00, p01), ph1 = pkbf(p02, p03);
            u32 ph2 = pkbf(p10, p11), ph3 = pkbf(p12, p13);

            const char* v0p = st + ST_VTHI + g*272     + (cb + 2*t)*2;
            const char* v1p = st + ST_VTHI + (8+g)*272 + (cb + 2*t)*2;
            u32 vh0a = *(const u32*)v0p,        vh0b = *(const u32*)(v0p+16);
            u32 vh1a = *(const u32*)v1p,        vh1b = *(const u32*)(v1p+16);

            mma16816(ctx0[0],ctx0[1],ctx0[2],ctx0[3], ph0,ph1,ph2,ph3, vh0a,vh0b);
            mma16816(ctx1[0],ctx1[1],ctx1[2],ctx1[3], ph0,ph1,ph2,ph3, vh1a,vh1b);
        }
        __syncthreads();
    }

    lA += __shfl_xor_sync(0xffffffffu, lA, 1);
    lA += __shfl_xor_sync(0xffffffffu, lA, 2);
    lB += __shfl_xor_sync(0xffffffffu, lB, 1);
    lB += __shfl_xor_sync(0xffffffffu, lB, 2);
    float invA = 1.0f / lA;
    float invB = 1.0f / lB;

    int rowA = qt*128 + w*16 + g;
    int rowB = rowA + 8;
    float* outA = g_ctx + ((u64)b*1024 + rowA)*64 + h*16;
    float* outB = g_ctx + ((u64)b*1024 + rowB)*64 + h*16;
    *(float2*)(outA + 2*t)     = make_float2(ctx0[0]*invA, ctx0[1]*invA);
    *(float2*)(outA + 2*t + 8) = make_float2(ctx1[0]*invA, ctx1[1]*invA);
    *(float2*)(outB + 2*t)     = make_float2(ctx0[2]*invB, ctx0[3]*invB);
    *(float2*)(outB + 2*t + 8) = make_float2(ctx1[2]*invB, ctx1[3]*invB);
}

// ---------------------------------------------------------------------------
// Output projection via mma.sync (unchanged from R16).
// ---------------------------------------------------------------------------
__global__ void __launch_bounds__(128) proj_kernel(const float* __restrict__ bp,
                                                   float* __restrict__ out) {
    int tid = threadIdx.x;
    int w    = tid >> 5;
    int lane = tid & 31;
    int g    = lane >> 2;
    int t    = lane & 3;

    int rowA = blockIdx.x*64 + w*16 + g;
    int rowB = rowA + 8;

    float acc[8][4];
#pragma unroll
    for (int nn = 0; nn < 8; nn++) {
        float2 bb = *(const float2*)&bp[nn*8 + 2*t];
        acc[nn][0] = bb.x; acc[nn][1] = bb.y;
        acc[nn][2] = bb.x; acc[nn][3] = bb.y;
    }

    const float* cA = g_ctx + (u64)rowA*64;
    const float* cB = g_ctx + (u64)rowB*64;

#pragma unroll
    for (int kk = 0; kk < 4; kk++) {
        int kb = kk*16;
        float2 x0 = *(const float2*)&cA[kb + 2*t];
        float2 x1 = *(const float2*)&cB[kb + 2*t];
        float2 x2 = *(const float2*)&cA[kb + 2*t + 8];
        float2 x3 = *(const float2*)&cB[kb + 2*t + 8];
        u32 ah0, al0, ah1, al1, ah2, al2, ah3, al3;
        split_pair(x0.x, x0.y, ah0, al0);
        split_pair(x1.x, x1.y, ah1, al1);
        split_pair(x2.x, x2.y, ah2, al2);
        split_pair(x3.x, x3.y, ah3, al3);

#pragma unroll
        for (int nn = 0; nn < 8; nn++) {
            int n = nn*8 + g;
            u32 bh0 = *(const u32*)&g_Wph[n*64 + kb + 2*t];
            u32 bh1 = *(const u32*)&g_Wph[n*64 + kb + 2*t + 8];
            u32 bl0 = *(const u32*)&g_Wpl[n*64 + kb + 2*t];
            u32 bl1 = *(const u32*)&g_Wpl[n*64 + kb + 2*t + 8];
            mma16816(acc[nn][0], acc[nn][1], acc[nn][2], acc[nn][3],
                     ah0, ah1, ah2, ah3, bh0, bh1);
            mma16816(acc[nn][0], acc[nn][1], acc[nn][2], acc[nn][3],
                     ah0, ah1, ah2, ah3, bl0, bl1);
            mma16816(acc[nn][0], acc[nn][1], acc[nn][2], acc[nn][3],
                     al0, al1, al2, al3, bh0, bh1);
        }
    }

#pragma unroll
    for (int nn = 0; nn < 8; nn++) {
        *(float2*)&out[(u64)rowA*64 + nn*8 + 2*t] = make_float2(acc[nn][0], acc[nn][1]);
        *(float2*)&out[(u64)rowB*64 + nn*8 + 2*t] = make_float2(acc[nn][2], acc[nn][3]);
    }
}

// ---------------------------------------------------------------------------
extern "C" void kernel_launch(void* const* d_in, const int* in_sizes, int n_in,
                              void* d_out, int out_size) {
    const float* x    = (const float*)d_in[0];
    const float* enc  = (const float*)d_in[1];
    const int*   msk  = (const int*)  d_in[2];
    const float* Wkv  = (const float*)d_in[3];
    const float* bkv  = (const float*)d_in[4];
    const float* Wq   = (const float*)d_in[5];
    const float* bq   = (const float*)d_in[6];
    const float* Wp   = (const float*)d_in[7];
    const float* bp   = (const float*)d_in[8];
    float* out = (float*)d_out;

    qkv_kernel<<<1024, 256>>>(x, enc, msk, Wkv, bkv, Wq, bq, Wp);
    attn_kernel<<<dim3(BB*NH, TT/128), 256>>>();
    proj_kernel<<<ROWS_TOTAL/64, 128>>>(bp, out);
}